// round 13
// baseline (speedup 1.0000x reference)
#include <cuda_runtime.h>
#include <mma.h>
#include <cstdint>

using namespace nvcuda;

#define N_NODES 100000
#define N_EDGES 400000
#define BATCH   2048
#define HD      128
#define NREL    100

// ---------------- scratch ----------------
__device__ __align__(16) float g_h[(size_t)N_NODES * HD];
__device__ __align__(16) float g_ssrc[N_NODES * 2];
__device__ __align__(16) float g_sdst[N_NODES * 2];
__device__ __align__(16) float g_rproj[NREL * HD];
__device__ __align__(16) float g_srel[NREL * 2];
__device__ __align__(16) float g_catproj[23 * HD];
__device__ __align__(16) float g_wext[128 * HD];    // rows: 0-99 W, 100-122 catproj, 123-127 zero
__device__ __align__(16) int   g_deg[N_NODES];
__device__ __align__(16) int   g_se[N_NODES * 2];
__device__ __align__(16) int   g_cur[N_NODES];
__device__ __align__(16) int2  g_edge[N_EDGES];
__device__ int g_total;

__device__ __forceinline__ float tanh_approx(float x) {
    float y;
    asm("tanh.approx.f32 %0, %1;" : "=f"(y) : "f"(x));
    return y;
}

// ---------------- prep: small GEMMs (K-split) + zero counters ----------------
__global__ void k_prep(const float* __restrict__ gtab, const float* __restrict__ atab,
                       const float* __restrict__ ltab, const float* __restrict__ init_rel,
                       const float* __restrict__ W,    const float* __restrict__ Wr,
                       const float* __restrict__ Wrel, const float* __restrict__ att_src,
                       float* __restrict__ rout) {
    const int b   = blockIdx.x;
    const int tid = threadIdx.x;  // 512

    if (b >= 223) {
        int i = (b - 223) * 512 + tid;
        if (i < N_NODES / 4) ((int4*)g_deg)[i] = make_int4(0, 0, 0, 0);
        if (b == 223 && tid == 0) g_total = 0;
        return;
    }

    const int d = tid & 127;
    const int s = tid >> 7;
    const float* arow;
    const float* Bmat;
    int klen;
    if (b < 100)       { arow = init_rel + b * 400;         Bmat = Wr;   klen = 400; }
    else if (b < 200)  { arow = init_rel + (b - 100) * 400; Bmat = Wrel; klen = 400; }
    else {
        int c = b - 200;
        if (c < 3)       { arow = gtab + c * 100;        Bmat = W + 100 * HD; }
        else if (c < 12) { arow = atab + (c - 3) * 100;  Bmat = W + 200 * HD; }
        else             { arow = ltab + (c - 12) * 100; Bmat = W + 300 * HD; }
        klen = 100;
    }
    const int span = klen >> 2;
    const int k0   = s * span;
    float acc = 0.f;
#pragma unroll 5
    for (int k = k0; k < k0 + span; k++) acc += arow[k] * Bmat[k * HD + d];

    __shared__ float part[512];
    part[tid] = acc;
    __syncthreads();
    float total = 0.f;
    if (tid < 128) {
        total = part[tid] + part[tid + 128] + part[tid + 256] + part[tid + 384];
        if (b < 100)      g_rproj[b * HD + d] = total;
        else if (b < 200) rout[(b - 100) * HD + d] = total;
        else              g_catproj[(b - 200) * HD + d] = total;
    }
    if (b < 100) {
        float p = (tid < 128) ? total * att_src[d] : 0.f;
#pragma unroll
        for (int o = 16; o > 0; o >>= 1) p += __shfl_xor_sync(0xffffffffu, p, o);
        __shared__ float ws[16];
        if ((tid & 31) == 0) ws[tid >> 5] = p;
        __syncthreads();
        if (tid == 0) {
            g_srel[b * 2 + 0] = ws[0] + ws[1];
            g_srel[b * 2 + 1] = ws[2] + ws[3];
        }
    }
}

// ---------------- extended weight matrix: [128 k][128 dim] row-major ----------------
__global__ void k_wext(const float* __restrict__ W) {
    int i = blockIdx.x * 256 + threadIdx.x;  // 16384 total
    int k = i >> 7, dim = i & 127;
    float v = 0.f;
    if (k < 100)      v = W[k * HD + dim];
    else if (k < 123) v = g_catproj[(k - 100) * HD + dim];
    g_wext[i] = v;
}

// ---------------- h projection: wmma tf32 (3xTF32 split), 128 nodes x 64 dims ----------------
// 256 threads = 8 warps; warp w handles node rows [w*16, w*16+16).
__global__ void __launch_bounds__(256, 2) k_h(
        const float* __restrict__ id_embed, const int* __restrict__ ent_feature,
        const float* __restrict__ att_src, const float* __restrict__ att_dst) {
    extern __shared__ float sm[];
    float* sX   = sm;               // 128 * 132 = 16896 (A tile; reused as staging)
    float* sW   = sX + 128 * 132;   // 128 * 64 = 8192 (B slice, row-major)
    float* satt = sW + 8192;        // 128: att_src slice + att_dst slice

    const int tid  = threadIdx.x;
    const int warp = tid >> 5;
    const int lane = tid & 31;
    const int nbase   = (blockIdx.x >> 1) * 128;
    const int half    = blockIdx.x & 1;
    const int dimbase = half * 64;

    // async fill: X cols 0..99
#pragma unroll
    for (int j = 0; j < 13; j++) {
        int i = tid + j * 256;
        if (i < 3200) {
            int node = i / 25, kq = i - node * 25;
            int ng = nbase + node;
            if (ng >= N_NODES) ng = N_NODES - 1;
            unsigned dst = (unsigned)__cvta_generic_to_shared(&sX[node * 132 + kq * 4]);
            asm volatile("cp.async.cg.shared.global [%0], [%1], 16;"
                         :: "r"(dst), "l"(&id_embed[(long)ng * 100 + kq * 4]));
        }
    }
    // async fill: B slice (128 rows x 64 cols) from g_wext
    {
        const float* wsrc = g_wext + dimbase;
#pragma unroll
        for (int j = 0; j < 8; j++) {
            int i = tid + j * 256;  // 2048 chunks of 16B
            int k = i >> 4, c = i & 15;
            unsigned dst = (unsigned)__cvta_generic_to_shared(&sW[k * 64 + c * 4]);
            asm volatile("cp.async.cg.shared.global [%0], [%1], 16;"
                         :: "r"(dst), "l"(wsrc + k * HD + c * 4));
        }
    }
    asm volatile("cp.async.commit_group;");

    if (tid < 64)  satt[tid] = att_src[dimbase + tid];
    else if (tid < 128) satt[64 + tid - 64] = att_dst[dimbase + tid - 64];

    // zero K 100..131 region of X
    for (int i = tid; i < 128 * 32; i += 256) {
        int node = i >> 5, c = i & 31;
        sX[node * 132 + 100 + c] = 0.f;
    }
    __syncthreads();
    // one-hot categorical columns (FIX: strided loop, 384 entries > 256 threads)
    for (int i = tid; i < 384; i += 256) {
        int node_l = i / 3, which = i - node_l * 3;
        int ng = nbase + node_l;
        if (ng >= N_NODES) ng = N_NODES - 1;
        int f = ent_feature[ng * 3 + which];
        int off = (which == 0) ? 0 : (which == 1) ? 3 : 12;
        sX[node_l * 132 + 100 + off + f] = 1.0f;
    }
    asm volatile("cp.async.wait_group 0;");
    __syncthreads();

    // mainloop: wmma 16x16x8 tf32 with 3xTF32 split
    wmma::fragment<wmma::accumulator, 16, 16, 8, float> acc[4];
#pragma unroll
    for (int nt = 0; nt < 4; nt++) wmma::fill_fragment(acc[nt], 0.0f);

    const float* arow = &sX[warp * 16 * 132];
#pragma unroll
    for (int kt = 0; kt < 16; kt++) {
        wmma::fragment<wmma::matrix_a, 16, 16, 8, wmma::precision::tf32, wmma::row_major> a_hi, a_lo;
        wmma::load_matrix_sync(a_hi, arow + kt * 8, 132);
#pragma unroll
        for (int i = 0; i < a_hi.num_elements; i++) {
            float v = a_hi.x[i];
            float h = wmma::__float_to_tf32(v);
            a_hi.x[i] = h;
            a_lo.x[i] = wmma::__float_to_tf32(v - h);
        }
#pragma unroll
        for (int nt = 0; nt < 4; nt++) {
            wmma::fragment<wmma::matrix_b, 16, 16, 8, wmma::precision::tf32, wmma::row_major> b_hi, b_lo;
            wmma::load_matrix_sync(b_hi, &sW[kt * 8 * 64 + nt * 16], 64);
#pragma unroll
            for (int i = 0; i < b_hi.num_elements; i++) {
                float v = b_hi.x[i];
                float h = wmma::__float_to_tf32(v);
                b_hi.x[i] = h;
                b_lo.x[i] = wmma::__float_to_tf32(v - h);
            }
            wmma::mma_sync(acc[nt], a_lo, b_hi, acc[nt]);
            wmma::mma_sync(acc[nt], a_hi, b_lo, acc[nt]);
            wmma::mma_sync(acc[nt], a_hi, b_hi, acc[nt]);
        }
    }

    // all warps done reading sX before staging overwrites it
    __syncthreads();

    // stage accumulators: warp-private 16x64 tile (pitch 68) in sX region
    float* stage = sX + warp * 1088;
#pragma unroll
    for (int nt = 0; nt < 4; nt++)
        wmma::store_matrix_sync(stage + nt * 16, acc[nt], 68, wmma::mem_row_major);
    __syncwarp();

    // h store: 16 rows x 64 cols, float2 per lane
#pragma unroll 4
    for (int r = 0; r < 16; r++) {
        int node = nbase + warp * 16 + r;
        if (node < N_NODES) {
            float2 v = *(const float2*)&stage[r * 68 + lane * 2];
            *(float2*)&g_h[(long)node * HD + dimbase + lane * 2] = v;
        }
    }
    // att dots: lane handles node = lane&15, dim segment = (lane>>4)*32
    {
        const int r   = lane & 15;
        const int seg = lane >> 4;
        const float* row = &stage[r * 68 + seg * 32];
        const float* as_ = &satt[seg * 32];
        const float* ad_ = &satt[64 + seg * 32];
        float ps = 0.f, pd = 0.f;
#pragma unroll 8
        for (int j = 0; j < 32; j++) {
            float h = row[j];
            ps += h * as_[j];
            pd += h * ad_[j];
        }
        ps += __shfl_xor_sync(0xffffffffu, ps, 16);
        pd += __shfl_xor_sync(0xffffffffu, pd, 16);
        int node = nbase + warp * 16 + r;
        if (seg == 0 && node < N_NODES) {
            g_ssrc[node * 2 + half] = ps;
            g_sdst[node * 2 + half] = pd;
        }
    }
}

// ---------------- CSR build (unordered segments) ----------------
__global__ void k_deg(const int* __restrict__ ei) {
    int e = blockIdx.x * 256 + threadIdx.x;
    if (e < N_EDGES) atomicAdd(&g_deg[ei[N_EDGES + e]], 1);
}

__global__ void k_assign() {
    const int n    = blockIdx.x * 256 + threadIdx.x;
    const int lane = threadIdx.x & 31;
    int deg = (n < N_NODES) ? g_deg[n] : 0;
    int scan = deg;
#pragma unroll
    for (int o = 1; o < 32; o <<= 1) {
        int v = __shfl_up_sync(0xffffffffu, scan, o);
        if (lane >= o) scan += v;
    }
    int wtot = __shfl_sync(0xffffffffu, scan, 31);
    int base = 0;
    if (lane == 31) base = atomicAdd(&g_total, wtot);
    base = __shfl_sync(0xffffffffu, base, 31);
    int start = base + scan - deg;
    if (n < N_NODES) {
        g_se[n * 2 + 0] = start;
        g_se[n * 2 + 1] = start + deg;
        g_cur[n] = start;
    }
}

__global__ void k_scatter(const int* __restrict__ ei, const int* __restrict__ etyp) {
    int e = blockIdx.x * 256 + threadIdx.x;
    if (e >= N_EDGES) return;
    const int dst = ei[N_EDGES + e];
    int pos = atomicAdd(&g_cur[dst], 1);
    g_edge[pos] = make_int2(ei[e], etyp[e]);
}

// ---------------- fused per-dst softmax + aggregation + tanh ----------------
__global__ void __launch_bounds__(256) k_agg(float* __restrict__ xout) {
    __shared__ float rp[NREL * HD];
    __shared__ int   sm_s[8][32];
    __shared__ int   sm_t[8][32];
    __shared__ float sm_a[8][2][32];
    const int tid = threadIdx.x;
    for (int i = tid; i < NREL * HD; i += 256) rp[i] = g_rproj[i];
    __syncthreads();

    const int lane = tid & 31;
    const int wid  = tid >> 5;
    const int head = lane >> 4;
    const int nwarps = gridDim.x * 8;

    for (int dst = blockIdx.x * 8 + wid; dst < N_NODES; dst += nwarps) {
        const int2 se  = ((const int2*)g_se)[dst];
        const int start = se.x, end = se.y;
        const int deg   = end - start;
        const float2 sd = ((const float2*)g_sdst)[dst];
        float4 acc = make_float4(0.f, 0.f, 0.f, 0.f);

        if (deg <= 32) {
            const int i = start + lane;
            const bool v = (i < end);
            int s = 0, t = 0;
            float l0 = -1e30f, l1 = -1e30f;
            if (v) {
                int2 ed = g_edge[i];
                s = ed.x; t = ed.y;
                float2 ss = ((const float2*)g_ssrc)[s];
                float2 sr = ((const float2*)g_srel)[t];
                l0 = ss.x + sr.x + sd.x; l0 = (l0 > 0.f) ? l0 : 0.2f * l0;
                l1 = ss.y + sr.y + sd.y; l1 = (l1 > 0.f) ? l1 : 0.2f * l1;
            }
            float m0 = l0, m1 = l1;
#pragma unroll
            for (int o = 16; o > 0; o >>= 1) {
                m0 = fmaxf(m0, __shfl_xor_sync(0xffffffffu, m0, o));
                m1 = fmaxf(m1, __shfl_xor_sync(0xffffffffu, m1, o));
            }
            float e0 = v ? __expf(l0 - m0) : 0.f;
            float e1 = v ? __expf(l1 - m1) : 0.f;
            float d0 = e0, d1 = e1;
#pragma unroll
            for (int o = 16; o > 0; o >>= 1) {
                d0 += __shfl_xor_sync(0xffffffffu, d0, o);
                d1 += __shfl_xor_sync(0xffffffffu, d1, o);
            }
            sm_s[wid][lane] = s;
            sm_t[wid][lane] = t;
            sm_a[wid][0][lane] = e0 / (d0 + 1e-16f);
            sm_a[wid][1][lane] = e1 / (d1 + 1e-16f);
            __syncwarp();
            for (int j = 0; j < deg; j++) {
                const int   sj = sm_s[wid][j];
                const int   tj = sm_t[wid][j];
                const float aj = sm_a[wid][head][j];
                float4 hv = *(const float4*)&g_h[(long)sj * HD + lane * 4];
                float4 rv = *(const float4*)&rp[tj * HD + lane * 4];
                acc.x += aj * (hv.x + rv.x);
                acc.y += aj * (hv.y + rv.y);
                acc.z += aj * (hv.z + rv.z);
                acc.w += aj * (hv.w + rv.w);
            }
        } else {
            float m0 = -1e30f, m1 = -1e30f;
            for (int i = start + lane; i < end; i += 32) {
                int2 ed = g_edge[i];
                float2 ss = ((const float2*)g_ssrc)[ed.x];
                float2 sr = ((const float2*)g_srel)[ed.y];
                float l0 = ss.x + sr.x + sd.x; l0 = (l0 > 0.f) ? l0 : 0.2f * l0;
                float l1 = ss.y + sr.y + sd.y; l1 = (l1 > 0.f) ? l1 : 0.2f * l1;
                m0 = fmaxf(m0, l0); m1 = fmaxf(m1, l1);
            }
#pragma unroll
            for (int o = 16; o > 0; o >>= 1) {
                m0 = fmaxf(m0, __shfl_xor_sync(0xffffffffu, m0, o));
                m1 = fmaxf(m1, __shfl_xor_sync(0xffffffffu, m1, o));
            }
            float d0 = 0.f, d1 = 0.f;
            for (int i = start + lane; i < end; i += 32) {
                int2 ed = g_edge[i];
                float2 ss = ((const float2*)g_ssrc)[ed.x];
                float2 sr = ((const float2*)g_srel)[ed.y];
                float l0 = ss.x + sr.x + sd.x; l0 = (l0 > 0.f) ? l0 : 0.2f * l0;
                float l1 = ss.y + sr.y + sd.y; l1 = (l1 > 0.f) ? l1 : 0.2f * l1;
                d0 += __expf(l0 - m0); d1 += __expf(l1 - m1);
            }
#pragma unroll
            for (int o = 16; o > 0; o >>= 1) {
                d0 += __shfl_xor_sync(0xffffffffu, d0, o);
                d1 += __shfl_xor_sync(0xffffffffu, d1, o);
            }
            const float inv0 = 1.f / (d0 + 1e-16f);
            const float inv1 = 1.f / (d1 + 1e-16f);
            for (int base = start; base < end; base += 32) {
                const int i = base + lane;
                int s = 0, t = 0;
                float a0 = 0.f, a1 = 0.f;
                if (i < end) {
                    int2 ed = g_edge[i];
                    s = ed.x; t = ed.y;
                    float2 ss = ((const float2*)g_ssrc)[s];
                    float2 sr = ((const float2*)g_srel)[t];
                    float l0 = ss.x + sr.x + sd.x; l0 = (l0 > 0.f) ? l0 : 0.2f * l0;
                    float l1 = ss.y + sr.y + sd.y; l1 = (l1 > 0.f) ? l1 : 0.2f * l1;
                    a0 = __expf(l0 - m0) * inv0;
                    a1 = __expf(l1 - m1) * inv1;
                }
                sm_s[wid][lane] = s;
                sm_t[wid][lane] = t;
                sm_a[wid][0][lane] = a0;
                sm_a[wid][1][lane] = a1;
                __syncwarp();
                const int cnt = min(32, end - base);
                for (int j = 0; j < cnt; j++) {
                    const int   sj = sm_s[wid][j];
                    const int   tj = sm_t[wid][j];
                    const float aj = sm_a[wid][head][j];
                    float4 hv = *(const float4*)&g_h[(long)sj * HD + lane * 4];
                    float4 rv = *(const float4*)&rp[tj * HD + lane * 4];
                    acc.x += aj * (hv.x + rv.x);
                    acc.y += aj * (hv.y + rv.y);
                    acc.z += aj * (hv.z + rv.z);
                    acc.w += aj * (hv.w + rv.w);
                }
                __syncwarp();
            }
        }
        acc.x = tanh_approx(acc.x);
        acc.y = tanh_approx(acc.y);
        acc.z = tanh_approx(acc.z);
        acc.w = tanh_approx(acc.w);
        *(float4*)&xout[(long)dst * HD + lane * 4] = acc;
    }
}

__global__ void k_gather(const int* __restrict__ sub, const float* __restrict__ xout,
                         float* __restrict__ sub_emb) {
    int b = blockIdx.x;
    int d = threadIdx.x;
    sub_emb[(long)b * HD + d] = xout[(long)sub[b] * HD + d];
}

// ---------------- launch ----------------
extern "C" void kernel_launch(void* const* d_in, const int* in_sizes, int n_in,
                              void* d_out, int out_size) {
    const int*   edge_index  = (const int*)d_in[0];
    const int*   edge_type   = (const int*)d_in[1];
    const int*   ent_feature = (const int*)d_in[3];
    const int*   sub         = (const int*)d_in[4];
    const float* id_embed    = (const float*)d_in[7];
    const float* gender_tab  = (const float*)d_in[8];
    const float* age_tab     = (const float*)d_in[9];
    const float* level_tab   = (const float*)d_in[10];
    const float* init_rel    = (const float*)d_in[11];
    const float* W           = (const float*)d_in[12];
    const float* Wr          = (const float*)d_in[13];
    const float* att_src     = (const float*)d_in[14];
    const float* att_dst     = (const float*)d_in[15];
    const float* Wrel        = (const float*)d_in[16];

    float* out     = (float*)d_out;
    float* sub_emb = out;
    float* rout    = out + (long)BATCH * HD;
    float* xout    = rout + (long)NREL * HD;

    // k_h smem: 16896 + 8192 + 128 floats = 100,864 B
    const int smem_kh = (16896 + 8192 + 128) * 4;
    cudaFuncSetAttribute(k_h, cudaFuncAttributeMaxDynamicSharedMemorySize, smem_kh);

    k_prep<<<223 + 49, 512>>>(gender_tab, age_tab, level_tab, init_rel, W, Wr, Wrel,
                              att_src, rout);
    k_wext<<<64, 256>>>(W);
    k_deg<<<(N_EDGES + 255) / 256, 256>>>(edge_index);
    k_h<<<((N_NODES + 127) / 128) * 2, 256, smem_kh>>>(id_embed, ent_feature,
                                                       att_src, att_dst);  // idx 3
    k_assign<<<(N_NODES + 255) / 256, 256>>>();
    k_scatter<<<(N_EDGES + 255) / 256, 256>>>(edge_index, edge_type);
    k_agg<<<592, 256>>>(xout);
    k_gather<<<BATCH, 128>>>(sub, xout, sub_emb);
}

// round 14
// speedup vs baseline: 1.2563x; 1.2563x over previous
#include <cuda_runtime.h>
#include <mma.h>
#include <cstdint>

using namespace nvcuda;

#define N_NODES 100000
#define N_EDGES 400000
#define BATCH   2048
#define HD      128
#define NREL    100

// ---------------- scratch ----------------
__device__ __align__(16) float g_h[(size_t)N_NODES * HD];
__device__ __align__(16) float g_ssrc[N_NODES * 2];
__device__ __align__(16) float g_sdst[N_NODES * 2];
__device__ __align__(16) float g_rproj[NREL * HD];
__device__ __align__(16) float g_srel[NREL * 2];
__device__ __align__(16) float g_catproj[23 * HD];
__device__ __align__(16) float g_wext[128 * HD];    // tf32-rounded: 0-99 W, 100-122 catproj, 123-127 zero
__device__ __align__(16) int   g_deg[N_NODES];
__device__ __align__(16) int   g_se[N_NODES * 2];
__device__ __align__(16) int   g_cur[N_NODES];
__device__ __align__(16) int2  g_edge[N_EDGES];
__device__ int g_total;

__device__ __forceinline__ float tanh_approx(float x) {
    float y;
    asm("tanh.approx.f32 %0, %1;" : "=f"(y) : "f"(x));
    return y;
}

// ---------------- prep: small GEMMs (K-split) + zero counters ----------------
__global__ void k_prep(const float* __restrict__ gtab, const float* __restrict__ atab,
                       const float* __restrict__ ltab, const float* __restrict__ init_rel,
                       const float* __restrict__ W,    const float* __restrict__ Wr,
                       const float* __restrict__ Wrel, const float* __restrict__ att_src,
                       float* __restrict__ rout) {
    const int b   = blockIdx.x;
    const int tid = threadIdx.x;  // 512

    if (b >= 223) {
        int i = (b - 223) * 512 + tid;
        if (i < N_NODES / 4) ((int4*)g_deg)[i] = make_int4(0, 0, 0, 0);
        if (b == 223 && tid == 0) g_total = 0;
        return;
    }

    const int d = tid & 127;
    const int s = tid >> 7;
    const float* arow;
    const float* Bmat;
    int klen;
    if (b < 100)       { arow = init_rel + b * 400;         Bmat = Wr;   klen = 400; }
    else if (b < 200)  { arow = init_rel + (b - 100) * 400; Bmat = Wrel; klen = 400; }
    else {
        int c = b - 200;
        if (c < 3)       { arow = gtab + c * 100;        Bmat = W + 100 * HD; }
        else if (c < 12) { arow = atab + (c - 3) * 100;  Bmat = W + 200 * HD; }
        else             { arow = ltab + (c - 12) * 100; Bmat = W + 300 * HD; }
        klen = 100;
    }
    const int span = klen >> 2;
    const int k0   = s * span;
    float acc = 0.f;
#pragma unroll 5
    for (int k = k0; k < k0 + span; k++) acc += arow[k] * Bmat[k * HD + d];

    __shared__ float part[512];
    part[tid] = acc;
    __syncthreads();
    float total = 0.f;
    if (tid < 128) {
        total = part[tid] + part[tid + 128] + part[tid + 256] + part[tid + 384];
        if (b < 100)      g_rproj[b * HD + d] = total;
        else if (b < 200) rout[(b - 100) * HD + d] = total;
        else              g_catproj[(b - 200) * HD + d] = total;
    }
    if (b < 100) {
        float p = (tid < 128) ? total * att_src[d] : 0.f;
#pragma unroll
        for (int o = 16; o > 0; o >>= 1) p += __shfl_xor_sync(0xffffffffu, p, o);
        __shared__ float ws[16];
        if ((tid & 31) == 0) ws[tid >> 5] = p;
        __syncthreads();
        if (tid == 0) {
            g_srel[b * 2 + 0] = ws[0] + ws[1];
            g_srel[b * 2 + 1] = ws[2] + ws[3];
        }
    }
}

// ---------------- extended weight matrix, PRE-ROUNDED to tf32 ----------------
__global__ void k_wext(const float* __restrict__ W) {
    int i = blockIdx.x * 256 + threadIdx.x;  // 16384 total
    int k = i >> 7, dim = i & 127;
    float v = 0.f;
    if (k < 100)      v = W[k * HD + dim];
    else if (k < 123) v = g_catproj[(k - 100) * HD + dim];
    uint32_t t;
    asm("cvt.rna.tf32.f32 %0, %1;" : "=r"(t) : "f"(v));
    g_wext[i] = __uint_as_float(t);
}

// ---------------- h projection: wmma tf32 single-pass, 128 nodes x 64 dims ----------------
// 256 threads = 8 warps; warp w handles node rows [w*16, w*16+16).
__global__ void __launch_bounds__(256, 2) k_h(
        const float* __restrict__ id_embed, const int* __restrict__ ent_feature,
        const float* __restrict__ att_src, const float* __restrict__ att_dst) {
    extern __shared__ float sm[];
    float* sX   = sm;               // 128 * 132 = 16896 (A tile; reused as staging)
    float* sW   = sX + 128 * 132;   // 128 * 64 = 8192 (B slice, tf32-rounded, row-major)
    float* satt = sW + 8192;        // 128

    const int tid  = threadIdx.x;
    const int warp = tid >> 5;
    const int lane = tid & 31;
    const int nbase   = (blockIdx.x >> 1) * 128;
    const int half    = blockIdx.x & 1;
    const int dimbase = half * 64;

    // async fill: X cols 0..99
#pragma unroll
    for (int j = 0; j < 13; j++) {
        int i = tid + j * 256;
        if (i < 3200) {
            int node = i / 25, kq = i - node * 25;
            int ng = nbase + node;
            if (ng >= N_NODES) ng = N_NODES - 1;
            unsigned dst = (unsigned)__cvta_generic_to_shared(&sX[node * 132 + kq * 4]);
            asm volatile("cp.async.cg.shared.global [%0], [%1], 16;"
                         :: "r"(dst), "l"(&id_embed[(long)ng * 100 + kq * 4]));
        }
    }
    // async fill: B slice (128 rows x 64 cols, already tf32-rounded)
    {
        const float* wsrc = g_wext + dimbase;
#pragma unroll
        for (int j = 0; j < 8; j++) {
            int i = tid + j * 256;  // 2048 chunks of 16B
            int k = i >> 4, c = i & 15;
            unsigned dst = (unsigned)__cvta_generic_to_shared(&sW[k * 64 + c * 4]);
            asm volatile("cp.async.cg.shared.global [%0], [%1], 16;"
                         :: "r"(dst), "l"(wsrc + k * HD + c * 4));
        }
    }
    asm volatile("cp.async.commit_group;");

    if (tid < 64)  satt[tid] = att_src[dimbase + tid];
    else if (tid < 128) satt[64 + tid - 64] = att_dst[dimbase + tid - 64];

    // zero K 100..131 region of X
    for (int i = tid; i < 128 * 32; i += 256) {
        int node = i >> 5, c = i & 31;
        sX[node * 132 + 100 + c] = 0.f;
    }
    __syncthreads();
    // one-hot categorical columns (strided: 384 entries, 256 threads)
    for (int i = tid; i < 384; i += 256) {
        int node_l = i / 3, which = i - node_l * 3;
        int ng = nbase + node_l;
        if (ng >= N_NODES) ng = N_NODES - 1;
        int f = ent_feature[ng * 3 + which];
        int off = (which == 0) ? 0 : (which == 1) ? 3 : 12;
        sX[node_l * 132 + 100 + off + f] = 1.0f;
    }
    asm volatile("cp.async.wait_group 0;");
    __syncthreads();

    // mainloop: single-pass wmma 16x16x8 tf32
    wmma::fragment<wmma::accumulator, 16, 16, 8, float> acc[4];
#pragma unroll
    for (int nt = 0; nt < 4; nt++) wmma::fill_fragment(acc[nt], 0.0f);

    const float* arow = &sX[warp * 16 * 132];
#pragma unroll
    for (int kt = 0; kt < 16; kt++) {
        wmma::fragment<wmma::matrix_a, 16, 16, 8, wmma::precision::tf32, wmma::row_major> a;
        wmma::load_matrix_sync(a, arow + kt * 8, 132);
#pragma unroll
        for (int i = 0; i < a.num_elements; i++) a.x[i] = wmma::__float_to_tf32(a.x[i]);
#pragma unroll
        for (int nt = 0; nt < 4; nt++) {
            wmma::fragment<wmma::matrix_b, 16, 16, 8, wmma::precision::tf32, wmma::row_major> b;
            wmma::load_matrix_sync(b, &sW[kt * 8 * 64 + nt * 16], 64);
            wmma::mma_sync(acc[nt], a, b, acc[nt]);
        }
    }

    // all warps done reading sX before staging overwrites it
    __syncthreads();

    // stage accumulators: warp-private 16x64 tile (pitch 68) in sX region
    float* stage = sX + warp * 1088;
#pragma unroll
    for (int nt = 0; nt < 4; nt++)
        wmma::store_matrix_sync(stage + nt * 16, acc[nt], 68, wmma::mem_row_major);
    __syncwarp();

    // h store: 16 rows x 64 cols, float2 per lane
#pragma unroll 4
    for (int r = 0; r < 16; r++) {
        int node = nbase + warp * 16 + r;
        if (node < N_NODES) {
            float2 v = *(const float2*)&stage[r * 68 + lane * 2];
            *(float2*)&g_h[(long)node * HD + dimbase + lane * 2] = v;
        }
    }
    // att dots: lane handles node = lane&15, dim segment = (lane>>4)*32
    {
        const int r   = lane & 15;
        const int seg = lane >> 4;
        const float* row = &stage[r * 68 + seg * 32];
        const float* as_ = &satt[seg * 32];
        const float* ad_ = &satt[64 + seg * 32];
        float ps = 0.f, pd = 0.f;
#pragma unroll 8
        for (int j = 0; j < 32; j++) {
            float h = row[j];
            ps += h * as_[j];
            pd += h * ad_[j];
        }
        ps += __shfl_xor_sync(0xffffffffu, ps, 16);
        pd += __shfl_xor_sync(0xffffffffu, pd, 16);
        int node = nbase + warp * 16 + r;
        if (seg == 0 && node < N_NODES) {
            g_ssrc[node * 2 + half] = ps;
            g_sdst[node * 2 + half] = pd;
        }
    }
}

// ---------------- CSR build (unordered segments) ----------------
__global__ void k_deg(const int* __restrict__ ei) {
    int e = blockIdx.x * 256 + threadIdx.x;
    if (e < N_EDGES) atomicAdd(&g_deg[ei[N_EDGES + e]], 1);
}

__global__ void k_assign() {
    const int n    = blockIdx.x * 256 + threadIdx.x;
    const int lane = threadIdx.x & 31;
    int deg = (n < N_NODES) ? g_deg[n] : 0;
    int scan = deg;
#pragma unroll
    for (int o = 1; o < 32; o <<= 1) {
        int v = __shfl_up_sync(0xffffffffu, scan, o);
        if (lane >= o) scan += v;
    }
    int wtot = __shfl_sync(0xffffffffu, scan, 31);
    int base = 0;
    if (lane == 31) base = atomicAdd(&g_total, wtot);
    base = __shfl_sync(0xffffffffu, base, 31);
    int start = base + scan - deg;
    if (n < N_NODES) {
        g_se[n * 2 + 0] = start;
        g_se[n * 2 + 1] = start + deg;
        g_cur[n] = start;
    }
}

__global__ void k_scatter(const int* __restrict__ ei, const int* __restrict__ etyp) {
    int e = blockIdx.x * 256 + threadIdx.x;
    if (e >= N_EDGES) return;
    const int dst = ei[N_EDGES + e];
    int pos = atomicAdd(&g_cur[dst], 1);
    g_edge[pos] = make_int2(ei[e], etyp[e]);
}

// ---------------- fused per-dst softmax + aggregation + tanh ----------------
__global__ void __launch_bounds__(256) k_agg(float* __restrict__ xout) {
    __shared__ float rp[NREL * HD];
    __shared__ int   sm_s[8][32];
    __shared__ int   sm_t[8][32];
    __shared__ float sm_a[8][2][32];
    const int tid = threadIdx.x;
    for (int i = tid; i < NREL * HD; i += 256) rp[i] = g_rproj[i];
    __syncthreads();

    const int lane = tid & 31;
    const int wid  = tid >> 5;
    const int head = lane >> 4;
    const int nwarps = gridDim.x * 8;

    for (int dst = blockIdx.x * 8 + wid; dst < N_NODES; dst += nwarps) {
        const int2 se  = ((const int2*)g_se)[dst];
        const int start = se.x, end = se.y;
        const int deg   = end - start;
        const float2 sd = ((const float2*)g_sdst)[dst];
        float4 acc = make_float4(0.f, 0.f, 0.f, 0.f);

        if (deg <= 32) {
            const int i = start + lane;
            const bool v = (i < end);
            int s = 0, t = 0;
            float l0 = -1e30f, l1 = -1e30f;
            if (v) {
                int2 ed = g_edge[i];
                s = ed.x; t = ed.y;
                float2 ss = ((const float2*)g_ssrc)[s];
                float2 sr = ((const float2*)g_srel)[t];
                l0 = ss.x + sr.x + sd.x; l0 = (l0 > 0.f) ? l0 : 0.2f * l0;
                l1 = ss.y + sr.y + sd.y; l1 = (l1 > 0.f) ? l1 : 0.2f * l1;
            }
            float m0 = l0, m1 = l1;
#pragma unroll
            for (int o = 16; o > 0; o >>= 1) {
                m0 = fmaxf(m0, __shfl_xor_sync(0xffffffffu, m0, o));
                m1 = fmaxf(m1, __shfl_xor_sync(0xffffffffu, m1, o));
            }
            float e0 = v ? __expf(l0 - m0) : 0.f;
            float e1 = v ? __expf(l1 - m1) : 0.f;
            float d0 = e0, d1 = e1;
#pragma unroll
            for (int o = 16; o > 0; o >>= 1) {
                d0 += __shfl_xor_sync(0xffffffffu, d0, o);
                d1 += __shfl_xor_sync(0xffffffffu, d1, o);
            }
            sm_s[wid][lane] = s;
            sm_t[wid][lane] = t;
            sm_a[wid][0][lane] = e0 / (d0 + 1e-16f);
            sm_a[wid][1][lane] = e1 / (d1 + 1e-16f);
            __syncwarp();
            for (int j = 0; j < deg; j++) {
                const int   sj = sm_s[wid][j];
                const int   tj = sm_t[wid][j];
                const float aj = sm_a[wid][head][j];
                float4 hv = *(const float4*)&g_h[(long)sj * HD + lane * 4];
                float4 rv = *(const float4*)&rp[tj * HD + lane * 4];
                acc.x += aj * (hv.x + rv.x);
                acc.y += aj * (hv.y + rv.y);
                acc.z += aj * (hv.z + rv.z);
                acc.w += aj * (hv.w + rv.w);
            }
        } else {
            float m0 = -1e30f, m1 = -1e30f;
            for (int i = start + lane; i < end; i += 32) {
                int2 ed = g_edge[i];
                float2 ss = ((const float2*)g_ssrc)[ed.x];
                float2 sr = ((const float2*)g_srel)[ed.y];
                float l0 = ss.x + sr.x + sd.x; l0 = (l0 > 0.f) ? l0 : 0.2f * l0;
                float l1 = ss.y + sr.y + sd.y; l1 = (l1 > 0.f) ? l1 : 0.2f * l1;
                m0 = fmaxf(m0, l0); m1 = fmaxf(m1, l1);
            }
#pragma unroll
            for (int o = 16; o > 0; o >>= 1) {
                m0 = fmaxf(m0, __shfl_xor_sync(0xffffffffu, m0, o));
                m1 = fmaxf(m1, __shfl_xor_sync(0xffffffffu, m1, o));
            }
            float d0 = 0.f, d1 = 0.f;
            for (int i = start + lane; i < end; i += 32) {
                int2 ed = g_edge[i];
                float2 ss = ((const float2*)g_ssrc)[ed.x];
                float2 sr = ((const float2*)g_srel)[ed.y];
                float l0 = ss.x + sr.x + sd.x; l0 = (l0 > 0.f) ? l0 : 0.2f * l0;
                float l1 = ss.y + sr.y + sd.y; l1 = (l1 > 0.f) ? l1 : 0.2f * l1;
                d0 += __expf(l0 - m0); d1 += __expf(l1 - m1);
            }
#pragma unroll
            for (int o = 16; o > 0; o >>= 1) {
                d0 += __shfl_xor_sync(0xffffffffu, d0, o);
                d1 += __shfl_xor_sync(0xffffffffu, d1, o);
            }
            const float inv0 = 1.f / (d0 + 1e-16f);
            const float inv1 = 1.f / (d1 + 1e-16f);
            for (int base = start; base < end; base += 32) {
                const int i = base + lane;
                int s = 0, t = 0;
                float a0 = 0.f, a1 = 0.f;
                if (i < end) {
                    int2 ed = g_edge[i];
                    s = ed.x; t = ed.y;
                    float2 ss = ((const float2*)g_ssrc)[s];
                    float2 sr = ((const float2*)g_srel)[t];
                    float l0 = ss.x + sr.x + sd.x; l0 = (l0 > 0.f) ? l0 : 0.2f * l0;
                    float l1 = ss.y + sr.y + sd.y; l1 = (l1 > 0.f) ? l1 : 0.2f * l1;
                    a0 = __expf(l0 - m0) * inv0;
                    a1 = __expf(l1 - m1) * inv1;
                }
                sm_s[wid][lane] = s;
                sm_t[wid][lane] = t;
                sm_a[wid][0][lane] = a0;
                sm_a[wid][1][lane] = a1;
                __syncwarp();
                const int cnt = min(32, end - base);
                for (int j = 0; j < cnt; j++) {
                    const int   sj = sm_s[wid][j];
                    const int   tj = sm_t[wid][j];
                    const float aj = sm_a[wid][head][j];
                    float4 hv = *(const float4*)&g_h[(long)sj * HD + lane * 4];
                    float4 rv = *(const float4*)&rp[tj * HD + lane * 4];
                    acc.x += aj * (hv.x + rv.x);
                    acc.y += aj * (hv.y + rv.y);
                    acc.z += aj * (hv.z + rv.z);
                    acc.w += aj * (hv.w + rv.w);
                }
                __syncwarp();
            }
        }
        acc.x = tanh_approx(acc.x);
        acc.y = tanh_approx(acc.y);
        acc.z = tanh_approx(acc.z);
        acc.w = tanh_approx(acc.w);
        *(float4*)&xout[(long)dst * HD + lane * 4] = acc;
    }
}

__global__ void k_gather(const int* __restrict__ sub, const float* __restrict__ xout,
                         float* __restrict__ sub_emb) {
    int b = blockIdx.x;
    int d = threadIdx.x;
    sub_emb[(long)b * HD + d] = xout[(long)sub[b] * HD + d];
}

// ---------------- launch ----------------
extern "C" void kernel_launch(void* const* d_in, const int* in_sizes, int n_in,
                              void* d_out, int out_size) {
    const int*   edge_index  = (const int*)d_in[0];
    const int*   edge_type   = (const int*)d_in[1];
    const int*   ent_feature = (const int*)d_in[3];
    const int*   sub         = (const int*)d_in[4];
    const float* id_embed    = (const float*)d_in[7];
    const float* gender_tab  = (const float*)d_in[8];
    const float* age_tab     = (const float*)d_in[9];
    const float* level_tab   = (const float*)d_in[10];
    const float* init_rel    = (const float*)d_in[11];
    const float* W           = (const float*)d_in[12];
    const float* Wr          = (const float*)d_in[13];
    const float* att_src     = (const float*)d_in[14];
    const float* att_dst     = (const float*)d_in[15];
    const float* Wrel        = (const float*)d_in[16];

    float* out     = (float*)d_out;
    float* sub_emb = out;
    float* rout    = out + (long)BATCH * HD;
    float* xout    = rout + (long)NREL * HD;

    // k_h smem: 16896 + 8192 + 128 floats = 100,864 B
    const int smem_kh = (16896 + 8192 + 128) * 4;
    cudaFuncSetAttribute(k_h, cudaFuncAttributeMaxDynamicSharedMemorySize, smem_kh);

    k_prep<<<223 + 49, 512>>>(gender_tab, age_tab, level_tab, init_rel, W, Wr, Wrel,
                              att_src, rout);
    k_wext<<<64, 256>>>(W);
    k_deg<<<(N_EDGES + 255) / 256, 256>>>(edge_index);
    k_h<<<((N_NODES + 127) / 128) * 2, 256, smem_kh>>>(id_embed, ent_feature,
                                                       att_src, att_dst);  // idx 3
    k_assign<<<(N_NODES + 255) / 256, 256>>>();
    k_scatter<<<(N_EDGES + 255) / 256, 256>>>(edge_index, edge_type);
    k_agg<<<592, 256>>>(xout);
    k_gather<<<BATCH, 128>>>(sub, xout, sub_emb);
}

// round 15
// speedup vs baseline: 1.3219x; 1.0522x over previous
#include <cuda_runtime.h>
#include <mma.h>
#include <cstdint>

using namespace nvcuda;

#define N_NODES 100000
#define N_EDGES 400000
#define BATCH   2048
#define HD      128
#define NREL    100

// ---------------- scratch ----------------
__device__ __align__(16) float g_h[(size_t)N_NODES * HD];
__device__ __align__(16) float g_ssrc[N_NODES * 2];
__device__ __align__(16) float g_sdst[N_NODES * 2];
__device__ __align__(16) float g_rproj[NREL * HD];
__device__ __align__(16) float g_srel[NREL * 2];
__device__ __align__(16) float g_catproj[23 * HD];
__device__ __align__(16) float g_wext[128 * HD];    // tf32-rounded: 0-99 W, 100-122 catproj, 123-127 zero
__device__ __align__(16) int   g_deg[N_NODES];
__device__ __align__(16) int   g_se[N_NODES * 2];
__device__ __align__(16) int   g_cur[N_NODES];
__device__ __align__(16) int2  g_edge[N_EDGES];
__device__ int g_total;

__device__ __forceinline__ float tanh_approx(float x) {
    float y;
    asm("tanh.approx.f32 %0, %1;" : "=f"(y) : "f"(x));
    return y;
}

// ---------------- prep: small GEMMs (K-split) + zero counters ----------------
__global__ void k_prep(const float* __restrict__ gtab, const float* __restrict__ atab,
                       const float* __restrict__ ltab, const float* __restrict__ init_rel,
                       const float* __restrict__ W,    const float* __restrict__ Wr,
                       const float* __restrict__ Wrel, const float* __restrict__ att_src,
                       float* __restrict__ rout) {
    const int b   = blockIdx.x;
    const int tid = threadIdx.x;  // 512

    if (b >= 223) {
        int i = (b - 223) * 512 + tid;
        if (i < N_NODES / 4) ((int4*)g_deg)[i] = make_int4(0, 0, 0, 0);
        if (b == 223 && tid == 0) g_total = 0;
        return;
    }

    const int d = tid & 127;
    const int s = tid >> 7;
    const float* arow;
    const float* Bmat;
    int klen;
    if (b < 100)       { arow = init_rel + b * 400;         Bmat = Wr;   klen = 400; }
    else if (b < 200)  { arow = init_rel + (b - 100) * 400; Bmat = Wrel; klen = 400; }
    else {
        int c = b - 200;
        if (c < 3)       { arow = gtab + c * 100;        Bmat = W + 100 * HD; }
        else if (c < 12) { arow = atab + (c - 3) * 100;  Bmat = W + 200 * HD; }
        else             { arow = ltab + (c - 12) * 100; Bmat = W + 300 * HD; }
        klen = 100;
    }
    const int span = klen >> 2;
    const int k0   = s * span;
    float acc = 0.f;
#pragma unroll 5
    for (int k = k0; k < k0 + span; k++) acc += arow[k] * Bmat[k * HD + d];

    __shared__ float part[512];
    part[tid] = acc;
    __syncthreads();
    float total = 0.f;
    if (tid < 128) {
        total = part[tid] + part[tid + 128] + part[tid + 256] + part[tid + 384];
        if (b < 100)      g_rproj[b * HD + d] = total;
        else if (b < 200) rout[(b - 100) * HD + d] = total;
        else              g_catproj[(b - 200) * HD + d] = total;
    }
    if (b < 100) {
        float p = (tid < 128) ? total * att_src[d] : 0.f;
#pragma unroll
        for (int o = 16; o > 0; o >>= 1) p += __shfl_xor_sync(0xffffffffu, p, o);
        __shared__ float ws[16];
        if ((tid & 31) == 0) ws[tid >> 5] = p;
        __syncthreads();
        if (tid == 0) {
            g_srel[b * 2 + 0] = ws[0] + ws[1];
            g_srel[b * 2 + 1] = ws[2] + ws[3];
        }
    }
}

// ---------------- extended weight matrix, PRE-ROUNDED to tf32 ----------------
__global__ void k_wext(const float* __restrict__ W) {
    int i = blockIdx.x * 256 + threadIdx.x;  // 16384 total
    int k = i >> 7, dim = i & 127;
    float v = 0.f;
    if (k < 100)      v = W[k * HD + dim];
    else if (k < 123) v = g_catproj[(k - 100) * HD + dim];
    uint32_t t;
    asm("cvt.rna.tf32.f32 %0, %1;" : "=r"(t) : "f"(v));
    g_wext[i] = __uint_as_float(t);
}

// ---------------- h projection: wmma tf32, 256 nodes x 64 dims per block ----------------
// 256 threads = 8 warps; warp w: nodes [w*32, w*32+32) x all 64 dims (mt=2, nt=4).
// K=128 split into 2 chunks of 64 (A staged per chunk).
__global__ void __launch_bounds__(256, 2) k_h(
        const float* __restrict__ id_embed, const int* __restrict__ ent_feature,
        const float* __restrict__ att_src, const float* __restrict__ att_dst) {
    extern __shared__ float sm[];
    float* sA   = sm;                // 256 * 68 = 17408 (A chunk; reused as staging)
    float* sB   = sA + 17408;        // 128 * 64 = 8192 (full-K B slice, tf32)
    float* satt = sB + 8192;         // 128

    const int tid  = threadIdx.x;
    const int warp = tid >> 5;
    const int lane = tid & 31;
    const int nbase   = (blockIdx.x >> 1) * 256;
    const int half    = blockIdx.x & 1;
    const int dimbase = half * 64;

    // async fill: B slice (128 K-rows x 64 dims, tf32-rounded)
    {
        const float* wsrc = g_wext + dimbase;
#pragma unroll
        for (int j = 0; j < 8; j++) {
            int i = tid + j * 256;  // 2048 chunks of 16B
            int k = i >> 4, c = i & 15;
            unsigned dst = (unsigned)__cvta_generic_to_shared(&sB[k * 64 + c * 4]);
            asm volatile("cp.async.cg.shared.global [%0], [%1], 16;"
                         :: "r"(dst), "l"(wsrc + k * HD + c * 4));
        }
    }
    if (tid < 64)       satt[tid] = att_src[dimbase + tid];
    else if (tid < 128) satt[tid] = att_dst[dimbase + tid - 64];

    wmma::fragment<wmma::accumulator, 16, 16, 8, float> acc[2][4];
#pragma unroll
    for (int mt = 0; mt < 2; mt++)
#pragma unroll
        for (int nt = 0; nt < 4; nt++) wmma::fill_fragment(acc[mt][nt], 0.0f);

#pragma unroll 1
    for (int ch = 0; ch < 2; ch++) {
        __syncthreads();  // prior chunk's reads of sA done
        if (ch == 0) {
            // K 0..63 from id_embed
#pragma unroll
            for (int j = 0; j < 16; j++) {
                int i = tid + j * 256;  // 4096
                int node = i >> 4, q = i & 15;
                int ng = nbase + node;
                if (ng >= N_NODES) ng = N_NODES - 1;
                unsigned dst = (unsigned)__cvta_generic_to_shared(&sA[node * 68 + q * 4]);
                asm volatile("cp.async.cg.shared.global [%0], [%1], 16;"
                             :: "r"(dst), "l"(&id_embed[(long)ng * 100 + q * 4]));
            }
            asm volatile("cp.async.commit_group;");
            asm volatile("cp.async.wait_group 0;");
            __syncthreads();
        } else {
            // K 64..127: cols 64..99 from id_embed (local 0..35), 100..122 one-hot, 123..127 zero
#pragma unroll
            for (int j = 0; j < 9; j++) {
                int i = tid + j * 256;  // 2304
                int node = i / 9, q = i - node * 9;
                int ng = nbase + node;
                if (ng >= N_NODES) ng = N_NODES - 1;
                unsigned dst = (unsigned)__cvta_generic_to_shared(&sA[node * 68 + q * 4]);
                asm volatile("cp.async.cg.shared.global [%0], [%1], 16;"
                             :: "r"(dst), "l"(&id_embed[(long)ng * 100 + 64 + q * 4]));
            }
            asm volatile("cp.async.commit_group;");
            // zero local cols 36..63 (7 float4 per node)
#pragma unroll
            for (int j = 0; j < 7; j++) {
                int i = tid + j * 256;  // 1792
                int node = i / 7, q = i - node * 7;
                *(float4*)&sA[node * 68 + 36 + q * 4] = make_float4(0.f, 0.f, 0.f, 0.f);
            }
            __syncthreads();  // zeros visible before one-hot writes
            // one-hot: local col = 36 + off + f
            for (int i = tid; i < 768; i += 256) {
                int node = i / 3, which = i - node * 3;
                int ng = nbase + node;
                if (ng >= N_NODES) ng = N_NODES - 1;
                int f = ent_feature[ng * 3 + which];
                int off = (which == 0) ? 0 : (which == 1) ? 3 : 12;
                sA[node * 68 + 36 + off + f] = 1.0f;
            }
            asm volatile("cp.async.wait_group 0;");
            __syncthreads();
        }

        // mainloop: 8 kt per chunk; per kt: 2 A-frags + 4 B-frags -> 8 MMAs
        const float* arow0 = &sA[(warp * 32) * 68];
        const float* arow1 = &sA[(warp * 32 + 16) * 68];
#pragma unroll
        for (int kt = 0; kt < 8; kt++) {
            wmma::fragment<wmma::matrix_a, 16, 16, 8, wmma::precision::tf32, wmma::row_major> a0, a1;
            wmma::load_matrix_sync(a0, arow0 + kt * 8, 68);
            wmma::load_matrix_sync(a1, arow1 + kt * 8, 68);
#pragma unroll
            for (int i = 0; i < a0.num_elements; i++) {
                a0.x[i] = wmma::__float_to_tf32(a0.x[i]);
                a1.x[i] = wmma::__float_to_tf32(a1.x[i]);
            }
#pragma unroll
            for (int nt = 0; nt < 4; nt++) {
                wmma::fragment<wmma::matrix_b, 16, 16, 8, wmma::precision::tf32, wmma::row_major> b;
                wmma::load_matrix_sync(b, &sB[(ch * 64 + kt * 8) * 64 + nt * 16], 64);
                wmma::mma_sync(acc[0][nt], a0, b, acc[0][nt]);
                wmma::mma_sync(acc[1][nt], a1, b, acc[1][nt]);
            }
        }
    }

    __syncthreads();  // all warps done reading sA

    // stage: warp-private 32x64 tile (pitch 68) in sA region
    float* stage = sA + warp * 2176;
#pragma unroll
    for (int mt = 0; mt < 2; mt++)
#pragma unroll
        for (int nt = 0; nt < 4; nt++)
            wmma::store_matrix_sync(stage + mt * 16 * 68 + nt * 16, acc[mt][nt], 68,
                                    wmma::mem_row_major);
    __syncwarp();

    // h store: 32 rows x 64 cols, float2 per lane
#pragma unroll 4
    for (int r = 0; r < 32; r++) {
        int node = nbase + warp * 32 + r;
        if (node < N_NODES) {
            float2 v = *(const float2*)&stage[r * 68 + lane * 2];
            *(float2*)&g_h[(long)node * HD + dimbase + lane * 2] = v;
        }
    }
    // att dots: lane = node (32 nodes per warp), full 64-dim dot, no shuffle
    {
        const float* row = &stage[lane * 68];
        float ps = 0.f, pd = 0.f;
#pragma unroll 8
        for (int j = 0; j < 64; j++) {
            float h = row[j];
            ps += h * satt[j];
            pd += h * satt[64 + j];
        }
        int node = nbase + warp * 32 + lane;
        if (node < N_NODES) {
            g_ssrc[node * 2 + half] = ps;
            g_sdst[node * 2 + half] = pd;
        }
    }
}

// ---------------- CSR build (unordered segments) ----------------
__global__ void k_deg(const int* __restrict__ ei) {
    int e = blockIdx.x * 256 + threadIdx.x;
    if (e < N_EDGES) atomicAdd(&g_deg[ei[N_EDGES + e]], 1);
}

__global__ void k_assign() {
    const int n    = blockIdx.x * 256 + threadIdx.x;
    const int lane = threadIdx.x & 31;
    int deg = (n < N_NODES) ? g_deg[n] : 0;
    int scan = deg;
#pragma unroll
    for (int o = 1; o < 32; o <<= 1) {
        int v = __shfl_up_sync(0xffffffffu, scan, o);
        if (lane >= o) scan += v;
    }
    int wtot = __shfl_sync(0xffffffffu, scan, 31);
    int base = 0;
    if (lane == 31) base = atomicAdd(&g_total, wtot);
    base = __shfl_sync(0xffffffffu, base, 31);
    int start = base + scan - deg;
    if (n < N_NODES) {
        g_se[n * 2 + 0] = start;
        g_se[n * 2 + 1] = start + deg;
        g_cur[n] = start;
    }
}

__global__ void k_scatter(const int* __restrict__ ei, const int* __restrict__ etyp) {
    int e = blockIdx.x * 256 + threadIdx.x;
    if (e >= N_EDGES) return;
    const int dst = ei[N_EDGES + e];
    int pos = atomicAdd(&g_cur[dst], 1);
    g_edge[pos] = make_int2(ei[e], etyp[e]);
}

// ---------------- fused per-dst softmax + aggregation + tanh ----------------
__global__ void __launch_bounds__(256) k_agg(float* __restrict__ xout) {
    __shared__ float rp[NREL * HD];
    __shared__ int   sm_s[8][32];
    __shared__ int   sm_t[8][32];
    __shared__ float sm_a[8][2][32];
    const int tid = threadIdx.x;
    for (int i = tid; i < NREL * HD; i += 256) rp[i] = g_rproj[i];
    __syncthreads();

    const int lane = tid & 31;
    const int wid  = tid >> 5;
    const int head = lane >> 4;
    const int nwarps = gridDim.x * 8;

    for (int dst = blockIdx.x * 8 + wid; dst < N_NODES; dst += nwarps) {
        const int2 se  = ((const int2*)g_se)[dst];
        const int start = se.x, end = se.y;
        const int deg   = end - start;
        const float2 sd = ((const float2*)g_sdst)[dst];
        float4 acc = make_float4(0.f, 0.f, 0.f, 0.f);

        if (deg <= 32) {
            const int i = start + lane;
            const bool v = (i < end);
            int s = 0, t = 0;
            float l0 = -1e30f, l1 = -1e30f;
            if (v) {
                int2 ed = g_edge[i];
                s = ed.x; t = ed.y;
                float2 ss = ((const float2*)g_ssrc)[s];
                float2 sr = ((const float2*)g_srel)[t];
                l0 = ss.x + sr.x + sd.x; l0 = (l0 > 0.f) ? l0 : 0.2f * l0;
                l1 = ss.y + sr.y + sd.y; l1 = (l1 > 0.f) ? l1 : 0.2f * l1;
            }
            float m0 = l0, m1 = l1;
#pragma unroll
            for (int o = 16; o > 0; o >>= 1) {
                m0 = fmaxf(m0, __shfl_xor_sync(0xffffffffu, m0, o));
                m1 = fmaxf(m1, __shfl_xor_sync(0xffffffffu, m1, o));
            }
            float e0 = v ? __expf(l0 - m0) : 0.f;
            float e1 = v ? __expf(l1 - m1) : 0.f;
            float d0 = e0, d1 = e1;
#pragma unroll
            for (int o = 16; o > 0; o >>= 1) {
                d0 += __shfl_xor_sync(0xffffffffu, d0, o);
                d1 += __shfl_xor_sync(0xffffffffu, d1, o);
            }
            sm_s[wid][lane] = s;
            sm_t[wid][lane] = t;
            sm_a[wid][0][lane] = e0 / (d0 + 1e-16f);
            sm_a[wid][1][lane] = e1 / (d1 + 1e-16f);
            __syncwarp();
            for (int j = 0; j < deg; j++) {
                const int   sj = sm_s[wid][j];
                const int   tj = sm_t[wid][j];
                const float aj = sm_a[wid][head][j];
                float4 hv = *(const float4*)&g_h[(long)sj * HD + lane * 4];
                float4 rv = *(const float4*)&rp[tj * HD + lane * 4];
                acc.x += aj * (hv.x + rv.x);
                acc.y += aj * (hv.y + rv.y);
                acc.z += aj * (hv.z + rv.z);
                acc.w += aj * (hv.w + rv.w);
            }
        } else {
            float m0 = -1e30f, m1 = -1e30f;
            for (int i = start + lane; i < end; i += 32) {
                int2 ed = g_edge[i];
                float2 ss = ((const float2*)g_ssrc)[ed.x];
                float2 sr = ((const float2*)g_srel)[ed.y];
                float l0 = ss.x + sr.x + sd.x; l0 = (l0 > 0.f) ? l0 : 0.2f * l0;
                float l1 = ss.y + sr.y + sd.y; l1 = (l1 > 0.f) ? l1 : 0.2f * l1;
                m0 = fmaxf(m0, l0); m1 = fmaxf(m1, l1);
            }
#pragma unroll
            for (int o = 16; o > 0; o >>= 1) {
                m0 = fmaxf(m0, __shfl_xor_sync(0xffffffffu, m0, o));
                m1 = fmaxf(m1, __shfl_xor_sync(0xffffffffu, m1, o));
            }
            float d0 = 0.f, d1 = 0.f;
            for (int i = start + lane; i < end; i += 32) {
                int2 ed = g_edge[i];
                float2 ss = ((const float2*)g_ssrc)[ed.x];
                float2 sr = ((const float2*)g_srel)[ed.y];
                float l0 = ss.x + sr.x + sd.x; l0 = (l0 > 0.f) ? l0 : 0.2f * l0;
                float l1 = ss.y + sr.y + sd.y; l1 = (l1 > 0.f) ? l1 : 0.2f * l1;
                d0 += __expf(l0 - m0); d1 += __expf(l1 - m1);
            }
#pragma unroll
            for (int o = 16; o > 0; o >>= 1) {
                d0 += __shfl_xor_sync(0xffffffffu, d0, o);
                d1 += __shfl_xor_sync(0xffffffffu, d1, o);
            }
            const float inv0 = 1.f / (d0 + 1e-16f);
            const float inv1 = 1.f / (d1 + 1e-16f);
            for (int base = start; base < end; base += 32) {
                const int i = base + lane;
                int s = 0, t = 0;
                float a0 = 0.f, a1 = 0.f;
                if (i < end) {
                    int2 ed = g_edge[i];
                    s = ed.x; t = ed.y;
                    float2 ss = ((const float2*)g_ssrc)[s];
                    float2 sr = ((const float2*)g_srel)[t];
                    float l0 = ss.x + sr.x + sd.x; l0 = (l0 > 0.f) ? l0 : 0.2f * l0;
                    float l1 = ss.y + sr.y + sd.y; l1 = (l1 > 0.f) ? l1 : 0.2f * l1;
                    a0 = __expf(l0 - m0) * inv0;
                    a1 = __expf(l1 - m1) * inv1;
                }
                sm_s[wid][lane] = s;
                sm_t[wid][lane] = t;
                sm_a[wid][0][lane] = a0;
                sm_a[wid][1][lane] = a1;
                __syncwarp();
                const int cnt = min(32, end - base);
                for (int j = 0; j < cnt; j++) {
                    const int   sj = sm_s[wid][j];
                    const int   tj = sm_t[wid][j];
                    const float aj = sm_a[wid][head][j];
                    float4 hv = *(const float4*)&g_h[(long)sj * HD + lane * 4];
                    float4 rv = *(const float4*)&rp[tj * HD + lane * 4];
                    acc.x += aj * (hv.x + rv.x);
                    acc.y += aj * (hv.y + rv.y);
                    acc.z += aj * (hv.z + rv.z);
                    acc.w += aj * (hv.w + rv.w);
                }
                __syncwarp();
            }
        }
        acc.x = tanh_approx(acc.x);
        acc.y = tanh_approx(acc.y);
        acc.z = tanh_approx(acc.z);
        acc.w = tanh_approx(acc.w);
        *(float4*)&xout[(long)dst * HD + lane * 4] = acc;
    }
}

__global__ void k_gather(const int* __restrict__ sub, const float* __restrict__ xout,
                         float* __restrict__ sub_emb) {
    int b = blockIdx.x;
    int d = threadIdx.x;
    sub_emb[(long)b * HD + d] = xout[(long)sub[b] * HD + d];
}

// ---------------- launch ----------------
extern "C" void kernel_launch(void* const* d_in, const int* in_sizes, int n_in,
                              void* d_out, int out_size) {
    const int*   edge_index  = (const int*)d_in[0];
    const int*   edge_type   = (const int*)d_in[1];
    const int*   ent_feature = (const int*)d_in[3];
    const int*   sub         = (const int*)d_in[4];
    const float* id_embed    = (const float*)d_in[7];
    const float* gender_tab  = (const float*)d_in[8];
    const float* age_tab     = (const float*)d_in[9];
    const float* level_tab   = (const float*)d_in[10];
    const float* init_rel    = (const float*)d_in[11];
    const float* W           = (const float*)d_in[12];
    const float* Wr          = (const float*)d_in[13];
    const float* att_src     = (const float*)d_in[14];
    const float* att_dst     = (const float*)d_in[15];
    const float* Wrel        = (const float*)d_in[16];

    float* out     = (float*)d_out;
    float* sub_emb = out;
    float* rout    = out + (long)BATCH * HD;
    float* xout    = rout + (long)NREL * HD;

    // k_h smem: 17408 + 8192 + 128 floats = 102,912 B
    const int smem_kh = (17408 + 8192 + 128) * 4;
    cudaFuncSetAttribute(k_h, cudaFuncAttributeMaxDynamicSharedMemorySize, smem_kh);

    k_prep<<<223 + 49, 512>>>(gender_tab, age_tab, level_tab, init_rel, W, Wr, Wrel,
                              att_src, rout);
    k_wext<<<64, 256>>>(W);
    k_deg<<<(N_EDGES + 255) / 256, 256>>>(edge_index);
    k_h<<<((N_NODES + 255) / 256) * 2, 256, smem_kh>>>(id_embed, ent_feature,
                                                       att_src, att_dst);  // idx 3
    k_assign<<<(N_NODES + 255) / 256, 256>>>();
    k_scatter<<<(N_EDGES + 255) / 256, 256>>>(edge_index, edge_type);
    k_agg<<<592, 256>>>(xout);
    k_gather<<<BATCH, 128>>>(sub, xout, sub_emb);
}

// round 16
// speedup vs baseline: 1.3550x; 1.0250x over previous
#include <cuda_runtime.h>
#include <mma.h>
#include <cstdint>

using namespace nvcuda;

#define N_NODES 100000
#define N_EDGES 400000
#define BATCH   2048
#define HD      128
#define NREL    100

// ---------------- scratch ----------------
__device__ __align__(16) float g_h[(size_t)N_NODES * HD];
__device__ __align__(16) float g_ssrc[N_NODES * 2];
__device__ __align__(16) float g_sdst[N_NODES * 2];
__device__ __align__(16) float g_rproj[NREL * HD];
__device__ __align__(16) float g_srel[NREL * 2];
__device__ __align__(16) float g_catproj[23 * HD];
__device__ __align__(16) float g_wext[128 * HD];    // tf32-rounded: 0-99 W, 100-122 catproj, 123-127 zero
__device__ __align__(16) int   g_deg[N_NODES];
__device__ __align__(16) int   g_se[N_NODES * 2];
__device__ __align__(16) int   g_cur[N_NODES];
__device__ __align__(16) int2  g_edge[N_EDGES];
__device__ int g_total;

__device__ __forceinline__ float tanh_approx(float x) {
    float y;
    asm("tanh.approx.f32 %0, %1;" : "=f"(y) : "f"(x));
    return y;
}

// ---------------- prep: small GEMMs (K-split) + zero counters ----------------
__global__ void k_prep(const float* __restrict__ gtab, const float* __restrict__ atab,
                       const float* __restrict__ ltab, const float* __restrict__ init_rel,
                       const float* __restrict__ W,    const float* __restrict__ Wr,
                       const float* __restrict__ Wrel, const float* __restrict__ att_src,
                       float* __restrict__ rout) {
    const int b   = blockIdx.x;
    const int tid = threadIdx.x;  // 512

    if (b >= 223) {
        int i = (b - 223) * 512 + tid;
        if (i < N_NODES / 4) ((int4*)g_deg)[i] = make_int4(0, 0, 0, 0);
        if (b == 223 && tid == 0) g_total = 0;
        return;
    }

    const int d = tid & 127;
    const int s = tid >> 7;
    const float* arow;
    const float* Bmat;
    int klen;
    if (b < 100)       { arow = init_rel + b * 400;         Bmat = Wr;   klen = 400; }
    else if (b < 200)  { arow = init_rel + (b - 100) * 400; Bmat = Wrel; klen = 400; }
    else {
        int c = b - 200;
        if (c < 3)       { arow = gtab + c * 100;        Bmat = W + 100 * HD; }
        else if (c < 12) { arow = atab + (c - 3) * 100;  Bmat = W + 200 * HD; }
        else             { arow = ltab + (c - 12) * 100; Bmat = W + 300 * HD; }
        klen = 100;
    }
    const int span = klen >> 2;
    const int k0   = s * span;
    float acc = 0.f;
#pragma unroll 5
    for (int k = k0; k < k0 + span; k++) acc += arow[k] * Bmat[k * HD + d];

    __shared__ float part[512];
    part[tid] = acc;
    __syncthreads();
    float total = 0.f;
    if (tid < 128) {
        total = part[tid] + part[tid + 128] + part[tid + 256] + part[tid + 384];
        if (b < 100)      g_rproj[b * HD + d] = total;
        else if (b < 200) rout[(b - 100) * HD + d] = total;
        else              g_catproj[(b - 200) * HD + d] = total;
    }
    if (b < 100) {
        float p = (tid < 128) ? total * att_src[d] : 0.f;
#pragma unroll
        for (int o = 16; o > 0; o >>= 1) p += __shfl_xor_sync(0xffffffffu, p, o);
        __shared__ float ws[16];
        if ((tid & 31) == 0) ws[tid >> 5] = p;
        __syncthreads();
        if (tid == 0) {
            g_srel[b * 2 + 0] = ws[0] + ws[1];
            g_srel[b * 2 + 1] = ws[2] + ws[3];
        }
    }
}

// ---------------- fused: tf32 W-ext pack (blocks 0..63) + degree histogram ----------------
__global__ void k_wextdeg(const float* __restrict__ W, const int* __restrict__ ei) {
    const int b = blockIdx.x;
    if (b < 64) {
        int i = b * 256 + threadIdx.x;  // 16384 total
        int k = i >> 7, dim = i & 127;
        float v = 0.f;
        if (k < 100)      v = W[k * HD + dim];
        else if (k < 123) v = g_catproj[(k - 100) * HD + dim];
        uint32_t t;
        asm("cvt.rna.tf32.f32 %0, %1;" : "=r"(t) : "f"(v));
        g_wext[i] = __uint_as_float(t);
    } else {
        int e = (b - 64) * 256 + threadIdx.x;
        if (e < N_EDGES) atomicAdd(&g_deg[ei[N_EDGES + e]], 1);
    }
}

// ---------------- h projection: wmma tf32, 128 nodes x 128 dims per block ----------------
// 256 threads = 8 warps; warp = (node-group 0..3) x (dim-half 0..1); warp tile 32x64.
__global__ void __launch_bounds__(256, 2) k_h(
        const float* __restrict__ id_embed, const int* __restrict__ ent_feature,
        const float* __restrict__ att_src, const float* __restrict__ att_dst) {
    extern __shared__ float sm[];
    float* sA   = sm;                 // 128 * 68 = 8704 (A chunk)
    float* sB   = sm + 8704;          // 128 * 128 = 16384 (full W-ext, tf32)
    float* satt = sm + 8704 + 16384;  // 256: att_src[128] + att_dst[128]
    // epilogue staging reuses sm[0 .. 17408) (sA + part of sB, both dead)

    const int tid  = threadIdx.x;
    const int warp = tid >> 5;
    const int lane = tid & 31;
    const int nbase   = blockIdx.x * 128;
    const int ngrp    = warp >> 1;
    const int half    = warp & 1;
    const int dimbase = half * 64;

    // async fill: full B (straight 64KB copy of g_wext)
#pragma unroll
    for (int j = 0; j < 16; j++) {
        int i = tid + j * 256;  // 4096 x 16B
        unsigned dst = (unsigned)__cvta_generic_to_shared(&sB[i * 4]);
        asm volatile("cp.async.cg.shared.global [%0], [%1], 16;"
                     :: "r"(dst), "l"(g_wext + i * 4));
    }
    if (tid < 128)      satt[tid] = att_src[tid];
    else                satt[128 + tid - 128] = att_dst[tid - 128];

    wmma::fragment<wmma::accumulator, 16, 16, 8, float> acc[2][4];
#pragma unroll
    for (int mt = 0; mt < 2; mt++)
#pragma unroll
        for (int nt = 0; nt < 4; nt++) wmma::fill_fragment(acc[mt][nt], 0.0f);

#pragma unroll 1
    for (int ch = 0; ch < 2; ch++) {
        __syncthreads();  // prior chunk's reads of sA done
        if (ch == 0) {
            // K 0..63 from id_embed: 128 nodes x 16 float4 = 2048
#pragma unroll
            for (int j = 0; j < 8; j++) {
                int i = tid + j * 256;
                int node = i >> 4, q = i & 15;
                int ng = nbase + node;
                if (ng >= N_NODES) ng = N_NODES - 1;
                unsigned dst = (unsigned)__cvta_generic_to_shared(&sA[node * 68 + q * 4]);
                asm volatile("cp.async.cg.shared.global [%0], [%1], 16;"
                             :: "r"(dst), "l"(&id_embed[(long)ng * 100 + q * 4]));
            }
            asm volatile("cp.async.commit_group;");
            asm volatile("cp.async.wait_group 0;");  // also waits B
            __syncthreads();
        } else {
            // K 64..99 -> local cols 0..35: 128 nodes x 9 float4 = 1152
#pragma unroll
            for (int j = 0; j < 5; j++) {
                int i = tid + j * 256;
                if (i < 1152) {
                    int node = i / 9, q = i - node * 9;
                    int ng = nbase + node;
                    if (ng >= N_NODES) ng = N_NODES - 1;
                    unsigned dst = (unsigned)__cvta_generic_to_shared(&sA[node * 68 + q * 4]);
                    asm volatile("cp.async.cg.shared.global [%0], [%1], 16;"
                                 :: "r"(dst), "l"(&id_embed[(long)ng * 100 + 64 + q * 4]));
                }
            }
            asm volatile("cp.async.commit_group;");
            // zero local cols 36..63: 128 x 7 float4 = 896
#pragma unroll
            for (int j = 0; j < 4; j++) {
                int i = tid + j * 256;
                if (i < 896) {
                    int node = i / 7, q = i - node * 7;
                    *(float4*)&sA[node * 68 + 36 + q * 4] = make_float4(0.f, 0.f, 0.f, 0.f);
                }
            }
            __syncthreads();  // zeros visible before one-hot writes
            // one-hot: local col = 36 + off + f (K 100..122)
            for (int i = tid; i < 384; i += 256) {
                int node = i / 3, which = i - node * 3;
                int ng = nbase + node;
                if (ng >= N_NODES) ng = N_NODES - 1;
                int f = ent_feature[ng * 3 + which];
                int off = (which == 0) ? 0 : (which == 1) ? 3 : 12;
                sA[node * 68 + 36 + off + f] = 1.0f;
            }
            asm volatile("cp.async.wait_group 0;");
            __syncthreads();
        }

        // mainloop: 8 kt per chunk; per kt: 2 A-frags + 4 B-frags -> 8 MMAs
        const float* arow0 = &sA[(ngrp * 32) * 68];
        const float* arow1 = arow0 + 16 * 68;
#pragma unroll
        for (int kt = 0; kt < 8; kt++) {
            wmma::fragment<wmma::matrix_a, 16, 16, 8, wmma::precision::tf32, wmma::row_major> a0, a1;
            wmma::load_matrix_sync(a0, arow0 + kt * 8, 68);
            wmma::load_matrix_sync(a1, arow1 + kt * 8, 68);
#pragma unroll
            for (int i = 0; i < a0.num_elements; i++) {
                a0.x[i] = wmma::__float_to_tf32(a0.x[i]);
                a1.x[i] = wmma::__float_to_tf32(a1.x[i]);
            }
#pragma unroll
            for (int nt = 0; nt < 4; nt++) {
                wmma::fragment<wmma::matrix_b, 16, 16, 8, wmma::precision::tf32, wmma::row_major> b;
                wmma::load_matrix_sync(b, &sB[(ch * 64 + kt * 8) * 128 + dimbase + nt * 16], 128);
                wmma::mma_sync(acc[0][nt], a0, b, acc[0][nt]);
                wmma::mma_sync(acc[1][nt], a1, b, acc[1][nt]);
            }
        }
    }

    __syncthreads();  // all warps done reading sA/sB

    // stage: warp-private 32x64 tile (pitch 68), region sm[0..17408)
    float* stage = sm + warp * 2176;
#pragma unroll
    for (int mt = 0; mt < 2; mt++)
#pragma unroll
        for (int nt = 0; nt < 4; nt++)
            wmma::store_matrix_sync(stage + mt * 16 * 68 + nt * 16, acc[mt][nt], 68,
                                    wmma::mem_row_major);
    __syncwarp();

    // h store: 32 rows x 64 cols (this warp's dim-half), float2 per lane
#pragma unroll 4
    for (int r = 0; r < 32; r++) {
        int node = nbase + ngrp * 32 + r;
        if (node < N_NODES) {
            float2 v = *(const float2*)&stage[r * 68 + lane * 2];
            *(float2*)&g_h[(long)node * HD + dimbase + lane * 2] = v;
        }
    }
    // att dots: lane = node (32 per warp), full 64-dim dot for this head, no shuffle
    {
        const float* row = &stage[lane * 68];
        float ps = 0.f, pd = 0.f;
#pragma unroll 8
        for (int j = 0; j < 64; j++) {
            float h = row[j];
            ps += h * satt[dimbase + j];
            pd += h * satt[128 + dimbase + j];
        }
        int node = nbase + ngrp * 32 + lane;
        if (node < N_NODES) {
            g_ssrc[node * 2 + half] = ps;
            g_sdst[node * 2 + half] = pd;
        }
    }
}

// ---------------- CSR build (unordered segments) ----------------
__global__ void k_assign() {
    const int n    = blockIdx.x * 256 + threadIdx.x;
    const int lane = threadIdx.x & 31;
    int deg = (n < N_NODES) ? g_deg[n] : 0;
    int scan = deg;
#pragma unroll
    for (int o = 1; o < 32; o <<= 1) {
        int v = __shfl_up_sync(0xffffffffu, scan, o);
        if (lane >= o) scan += v;
    }
    int wtot = __shfl_sync(0xffffffffu, scan, 31);
    int base = 0;
    if (lane == 31) base = atomicAdd(&g_total, wtot);
    base = __shfl_sync(0xffffffffu, base, 31);
    int start = base + scan - deg;
    if (n < N_NODES) {
        g_se[n * 2 + 0] = start;
        g_se[n * 2 + 1] = start + deg;
        g_cur[n] = start;
    }
}

__global__ void k_scatter(const int* __restrict__ ei, const int* __restrict__ etyp) {
    int e = blockIdx.x * 256 + threadIdx.x;
    if (e >= N_EDGES) return;
    const int dst = ei[N_EDGES + e];
    int pos = atomicAdd(&g_cur[dst], 1);
    g_edge[pos] = make_int2(ei[e], etyp[e]);
}

// ---------------- fused per-dst softmax + aggregation + tanh ----------------
__global__ void __launch_bounds__(256) k_agg(float* __restrict__ xout) {
    __shared__ float rp[NREL * HD];
    __shared__ int   sm_s[8][32];
    __shared__ int   sm_t[8][32];
    __shared__ float sm_a[8][2][32];
    const int tid = threadIdx.x;
    for (int i = tid; i < NREL * HD; i += 256) rp[i] = g_rproj[i];
    __syncthreads();

    const int lane = tid & 31;
    const int wid  = tid >> 5;
    const int head = lane >> 4;
    const int nwarps = gridDim.x * 8;

    for (int dst = blockIdx.x * 8 + wid; dst < N_NODES; dst += nwarps) {
        const int2 se  = ((const int2*)g_se)[dst];
        const int start = se.x, end = se.y;
        const int deg   = end - start;
        const float2 sd = ((const float2*)g_sdst)[dst];
        float4 acc = make_float4(0.f, 0.f, 0.f, 0.f);

        if (deg <= 32) {
            const int i = start + lane;
            const bool v = (i < end);
            int s = 0, t = 0;
            float l0 = -1e30f, l1 = -1e30f;
            if (v) {
                int2 ed = g_edge[i];
                s = ed.x; t = ed.y;
                float2 ss = ((const float2*)g_ssrc)[s];
                float2 sr = ((const float2*)g_srel)[t];
                l0 = ss.x + sr.x + sd.x; l0 = (l0 > 0.f) ? l0 : 0.2f * l0;
                l1 = ss.y + sr.y + sd.y; l1 = (l1 > 0.f) ? l1 : 0.2f * l1;
            }
            float m0 = l0, m1 = l1;
#pragma unroll
            for (int o = 16; o > 0; o >>= 1) {
                m0 = fmaxf(m0, __shfl_xor_sync(0xffffffffu, m0, o));
                m1 = fmaxf(m1, __shfl_xor_sync(0xffffffffu, m1, o));
            }
            float e0 = v ? __expf(l0 - m0) : 0.f;
            float e1 = v ? __expf(l1 - m1) : 0.f;
            float d0 = e0, d1 = e1;
#pragma unroll
            for (int o = 16; o > 0; o >>= 1) {
                d0 += __shfl_xor_sync(0xffffffffu, d0, o);
                d1 += __shfl_xor_sync(0xffffffffu, d1, o);
            }
            sm_s[wid][lane] = s;
            sm_t[wid][lane] = t;
            sm_a[wid][0][lane] = e0 / (d0 + 1e-16f);
            sm_a[wid][1][lane] = e1 / (d1 + 1e-16f);
            __syncwarp();
            for (int j = 0; j < deg; j++) {
                const int   sj = sm_s[wid][j];
                const int   tj = sm_t[wid][j];
                const float aj = sm_a[wid][head][j];
                float4 hv = *(const float4*)&g_h[(long)sj * HD + lane * 4];
                float4 rv = *(const float4*)&rp[tj * HD + lane * 4];
                acc.x += aj * (hv.x + rv.x);
                acc.y += aj * (hv.y + rv.y);
                acc.z += aj * (hv.z + rv.z);
                acc.w += aj * (hv.w + rv.w);
            }
        } else {
            float m0 = -1e30f, m1 = -1e30f;
            for (int i = start + lane; i < end; i += 32) {
                int2 ed = g_edge[i];
                float2 ss = ((const float2*)g_ssrc)[ed.x];
                float2 sr = ((const float2*)g_srel)[ed.y];
                float l0 = ss.x + sr.x + sd.x; l0 = (l0 > 0.f) ? l0 : 0.2f * l0;
                float l1 = ss.y + sr.y + sd.y; l1 = (l1 > 0.f) ? l1 : 0.2f * l1;
                m0 = fmaxf(m0, l0); m1 = fmaxf(m1, l1);
            }
#pragma unroll
            for (int o = 16; o > 0; o >>= 1) {
                m0 = fmaxf(m0, __shfl_xor_sync(0xffffffffu, m0, o));
                m1 = fmaxf(m1, __shfl_xor_sync(0xffffffffu, m1, o));
            }
            float d0 = 0.f, d1 = 0.f;
            for (int i = start + lane; i < end; i += 32) {
                int2 ed = g_edge[i];
                float2 ss = ((const float2*)g_ssrc)[ed.x];
                float2 sr = ((const float2*)g_srel)[ed.y];
                float l0 = ss.x + sr.x + sd.x; l0 = (l0 > 0.f) ? l0 : 0.2f * l0;
                float l1 = ss.y + sr.y + sd.y; l1 = (l1 > 0.f) ? l1 : 0.2f * l1;
                d0 += __expf(l0 - m0); d1 += __expf(l1 - m1);
            }
#pragma unroll
            for (int o = 16; o > 0; o >>= 1) {
                d0 += __shfl_xor_sync(0xffffffffu, d0, o);
                d1 += __shfl_xor_sync(0xffffffffu, d1, o);
            }
            const float inv0 = 1.f / (d0 + 1e-16f);
            const float inv1 = 1.f / (d1 + 1e-16f);
            for (int base = start; base < end; base += 32) {
                const int i = base + lane;
                int s = 0, t = 0;
                float a0 = 0.f, a1 = 0.f;
                if (i < end) {
                    int2 ed = g_edge[i];
                    s = ed.x; t = ed.y;
                    float2 ss = ((const float2*)g_ssrc)[s];
                    float2 sr = ((const float2*)g_srel)[t];
                    float l0 = ss.x + sr.x + sd.x; l0 = (l0 > 0.f) ? l0 : 0.2f * l0;
                    float l1 = ss.y + sr.y + sd.y; l1 = (l1 > 0.f) ? l1 : 0.2f * l1;
                    a0 = __expf(l0 - m0) * inv0;
                    a1 = __expf(l1 - m1) * inv1;
                }
                sm_s[wid][lane] = s;
                sm_t[wid][lane] = t;
                sm_a[wid][0][lane] = a0;
                sm_a[wid][1][lane] = a1;
                __syncwarp();
                const int cnt = min(32, end - base);
                for (int j = 0; j < cnt; j++) {
                    const int   sj = sm_s[wid][j];
                    const int   tj = sm_t[wid][j];
                    const float aj = sm_a[wid][head][j];
                    float4 hv = *(const float4*)&g_h[(long)sj * HD + lane * 4];
                    float4 rv = *(const float4*)&rp[tj * HD + lane * 4];
                    acc.x += aj * (hv.x + rv.x);
                    acc.y += aj * (hv.y + rv.y);
                    acc.z += aj * (hv.z + rv.z);
                    acc.w += aj * (hv.w + rv.w);
                }
                __syncwarp();
            }
        }
        acc.x = tanh_approx(acc.x);
        acc.y = tanh_approx(acc.y);
        acc.z = tanh_approx(acc.z);
        acc.w = tanh_approx(acc.w);
        *(float4*)&xout[(long)dst * HD + lane * 4] = acc;
    }
}

__global__ void k_gather(const int* __restrict__ sub, const float* __restrict__ xout,
                         float* __restrict__ sub_emb) {
    int b = blockIdx.x;
    int d = threadIdx.x;
    sub_emb[(long)b * HD + d] = xout[(long)sub[b] * HD + d];
}

// ---------------- launch ----------------
extern "C" void kernel_launch(void* const* d_in, const int* in_sizes, int n_in,
                              void* d_out, int out_size) {
    const int*   edge_index  = (const int*)d_in[0];
    const int*   edge_type   = (const int*)d_in[1];
    const int*   ent_feature = (const int*)d_in[3];
    const int*   sub         = (const int*)d_in[4];
    const float* id_embed    = (const float*)d_in[7];
    const float* gender_tab  = (const float*)d_in[8];
    const float* age_tab     = (const float*)d_in[9];
    const float* level_tab   = (const float*)d_in[10];
    const float* init_rel    = (const float*)d_in[11];
    const float* W           = (const float*)d_in[12];
    const float* Wr          = (const float*)d_in[13];
    const float* att_src     = (const float*)d_in[14];
    const float* att_dst     = (const float*)d_in[15];
    const float* Wrel        = (const float*)d_in[16];

    float* out     = (float*)d_out;
    float* sub_emb = out;
    float* rout    = out + (long)BATCH * HD;
    float* xout    = rout + (long)NREL * HD;

    // k_h smem: 8704 + 16384 + 256 floats = 101,376 B
    const int smem_kh = (8704 + 16384 + 256) * 4;
    cudaFuncSetAttribute(k_h, cudaFuncAttributeMaxDynamicSharedMemorySize, smem_kh);

    k_prep<<<223 + 49, 512>>>(gender_tab, age_tab, level_tab, init_rel, W, Wr, Wrel,
                              att_src, rout);
    k_wextdeg<<<64 + (N_EDGES + 255) / 256, 256>>>(W, edge_index);
    k_assign<<<(N_NODES + 255) / 256, 256>>>();
    k_h<<<(N_NODES + 127) / 128, 256, smem_kh>>>(id_embed, ent_feature,
                                                 att_src, att_dst);  // profile idx 3
    k_scatter<<<(N_EDGES + 255) / 256, 256>>>(edge_index, edge_type);
    k_agg<<<592, 256>>>(xout);
    k_gather<<<BATCH, 128>>>(sub, xout, sub_emb);
}

// round 17
// speedup vs baseline: 1.3942x; 1.0289x over previous
#include <cuda_runtime.h>
#include <mma.h>
#include <cstdint>

using namespace nvcuda;

#define N_NODES 100000
#define N_EDGES 400000
#define BATCH   2048
#define HD      128
#define NREL    100

// ---------------- scratch ----------------
__device__ __align__(16) float g_h[(size_t)N_NODES * HD];
__device__ __align__(16) float g_ssrc[N_NODES * 2];
__device__ __align__(16) float g_sdst[N_NODES * 2];
__device__ __align__(16) float g_rproj[NREL * HD];
__device__ __align__(16) float g_srel[NREL * 2];
__device__ __align__(16) float g_catproj[23 * HD];
__device__ __align__(16) float g_wext[128 * HD];    // tf32-rounded: 0-99 W, 100-122 catproj, 123-127 zero
__device__ __align__(16) int   g_deg[N_NODES];
__device__ __align__(16) int   g_se[N_NODES * 2];
__device__ __align__(16) int   g_cur[N_NODES];
__device__ __align__(16) int2  g_edge[N_EDGES];
__device__ int g_total;

__device__ __forceinline__ float tanh_approx(float x) {
    float y;
    asm("tanh.approx.f32 %0, %1;" : "=f"(y) : "f"(x));
    return y;
}

// ---------------- prep: small GEMMs (K-split) + zero counters ----------------
__global__ void k_prep(const float* __restrict__ gtab, const float* __restrict__ atab,
                       const float* __restrict__ ltab, const float* __restrict__ init_rel,
                       const float* __restrict__ W,    const float* __restrict__ Wr,
                       const float* __restrict__ Wrel, const float* __restrict__ att_src,
                       float* __restrict__ rout) {
    const int b   = blockIdx.x;
    const int tid = threadIdx.x;  // 512

    if (b >= 223) {
        int i = (b - 223) * 512 + tid;
        if (i < N_NODES / 4) ((int4*)g_deg)[i] = make_int4(0, 0, 0, 0);
        if (b == 223 && tid == 0) g_total = 0;
        return;
    }

    const int d = tid & 127;
    const int s = tid >> 7;
    const float* arow;
    const float* Bmat;
    int klen;
    if (b < 100)       { arow = init_rel + b * 400;         Bmat = Wr;   klen = 400; }
    else if (b < 200)  { arow = init_rel + (b - 100) * 400; Bmat = Wrel; klen = 400; }
    else {
        int c = b - 200;
        if (c < 3)       { arow = gtab + c * 100;        Bmat = W + 100 * HD; }
        else if (c < 12) { arow = atab + (c - 3) * 100;  Bmat = W + 200 * HD; }
        else             { arow = ltab + (c - 12) * 100; Bmat = W + 300 * HD; }
        klen = 100;
    }
    const int span = klen >> 2;
    const int k0   = s * span;
    float acc = 0.f;
#pragma unroll 5
    for (int k = k0; k < k0 + span; k++) acc += arow[k] * Bmat[k * HD + d];

    __shared__ float part[512];
    part[tid] = acc;
    __syncthreads();
    float total = 0.f;
    if (tid < 128) {
        total = part[tid] + part[tid + 128] + part[tid + 256] + part[tid + 384];
        if (b < 100)      g_rproj[b * HD + d] = total;
        else if (b < 200) rout[(b - 100) * HD + d] = total;
        else              g_catproj[(b - 200) * HD + d] = total;
    }
    if (b < 100) {
        float p = (tid < 128) ? total * att_src[d] : 0.f;
#pragma unroll
        for (int o = 16; o > 0; o >>= 1) p += __shfl_xor_sync(0xffffffffu, p, o);
        __shared__ float ws[16];
        if ((tid & 31) == 0) ws[tid >> 5] = p;
        __syncthreads();
        if (tid == 0) {
            g_srel[b * 2 + 0] = ws[0] + ws[1];
            g_srel[b * 2 + 1] = ws[2] + ws[3];
        }
    }
}

// ---------------- fused: tf32 W-ext pack (blocks 0..63) + degree histogram ----------------
__global__ void k_wextdeg(const float* __restrict__ W, const int* __restrict__ ei) {
    const int b = blockIdx.x;
    if (b < 64) {
        int i = b * 256 + threadIdx.x;  // 16384 total
        int k = i >> 7, dim = i & 127;
        float v = 0.f;
        if (k < 100)      v = W[k * HD + dim];
        else if (k < 123) v = g_catproj[(k - 100) * HD + dim];
        uint32_t t;
        asm("cvt.rna.tf32.f32 %0, %1;" : "=r"(t) : "f"(v));
        g_wext[i] = __uint_as_float(t);
    } else {
        int e = (b - 64) * 256 + threadIdx.x;
        if (e < N_EDGES) atomicAdd(&g_deg[ei[N_EDGES + e]], 1);
    }
}

// ---------------- h projection: wmma tf32, 128 nodes x 128 dims per block ----------------
__global__ void __launch_bounds__(256, 2) k_h(
        const float* __restrict__ id_embed, const int* __restrict__ ent_feature,
        const float* __restrict__ att_src, const float* __restrict__ att_dst) {
    extern __shared__ float sm[];
    float* sA   = sm;                 // 128 * 68 = 8704 (A chunk)
    float* sB   = sm + 8704;          // 128 * 128 = 16384 (full W-ext, tf32)
    float* satt = sm + 8704 + 16384;  // 256: att_src[128] + att_dst[128]

    const int tid  = threadIdx.x;
    const int warp = tid >> 5;
    const int lane = tid & 31;
    const int nbase   = blockIdx.x * 128;
    const int ngrp    = warp >> 1;
    const int half    = warp & 1;
    const int dimbase = half * 64;

    // async fill: full B (straight 64KB copy of g_wext)
#pragma unroll
    for (int j = 0; j < 16; j++) {
        int i = tid + j * 256;  // 4096 x 16B
        unsigned dst = (unsigned)__cvta_generic_to_shared(&sB[i * 4]);
        asm volatile("cp.async.cg.shared.global [%0], [%1], 16;"
                     :: "r"(dst), "l"(g_wext + i * 4));
    }
    if (tid < 128)      satt[tid] = att_src[tid];
    else                satt[128 + tid - 128] = att_dst[tid - 128];

    wmma::fragment<wmma::accumulator, 16, 16, 8, float> acc[2][4];
#pragma unroll
    for (int mt = 0; mt < 2; mt++)
#pragma unroll
        for (int nt = 0; nt < 4; nt++) wmma::fill_fragment(acc[mt][nt], 0.0f);

#pragma unroll 1
    for (int ch = 0; ch < 2; ch++) {
        __syncthreads();
        if (ch == 0) {
#pragma unroll
            for (int j = 0; j < 8; j++) {
                int i = tid + j * 256;
                int node = i >> 4, q = i & 15;
                int ng = nbase + node;
                if (ng >= N_NODES) ng = N_NODES - 1;
                unsigned dst = (unsigned)__cvta_generic_to_shared(&sA[node * 68 + q * 4]);
                asm volatile("cp.async.cg.shared.global [%0], [%1], 16;"
                             :: "r"(dst), "l"(&id_embed[(long)ng * 100 + q * 4]));
            }
            asm volatile("cp.async.commit_group;");
            asm volatile("cp.async.wait_group 0;");
            __syncthreads();
        } else {
#pragma unroll
            for (int j = 0; j < 5; j++) {
                int i = tid + j * 256;
                if (i < 1152) {
                    int node = i / 9, q = i - node * 9;
                    int ng = nbase + node;
                    if (ng >= N_NODES) ng = N_NODES - 1;
                    unsigned dst = (unsigned)__cvta_generic_to_shared(&sA[node * 68 + q * 4]);
                    asm volatile("cp.async.cg.shared.global [%0], [%1], 16;"
                                 :: "r"(dst), "l"(&id_embed[(long)ng * 100 + 64 + q * 4]));
                }
            }
            asm volatile("cp.async.commit_group;");
#pragma unroll
            for (int j = 0; j < 4; j++) {
                int i = tid + j * 256;
                if (i < 896) {
                    int node = i / 7, q = i - node * 7;
                    *(float4*)&sA[node * 68 + 36 + q * 4] = make_float4(0.f, 0.f, 0.f, 0.f);
                }
            }
            __syncthreads();
            for (int i = tid; i < 384; i += 256) {
                int node = i / 3, which = i - node * 3;
                int ng = nbase + node;
                if (ng >= N_NODES) ng = N_NODES - 1;
                int f = ent_feature[ng * 3 + which];
                int off = (which == 0) ? 0 : (which == 1) ? 3 : 12;
                sA[node * 68 + 36 + off + f] = 1.0f;
            }
            asm volatile("cp.async.wait_group 0;");
            __syncthreads();
        }

        const float* arow0 = &sA[(ngrp * 32) * 68];
        const float* arow1 = arow0 + 16 * 68;
#pragma unroll
        for (int kt = 0; kt < 8; kt++) {
            wmma::fragment<wmma::matrix_a, 16, 16, 8, wmma::precision::tf32, wmma::row_major> a0, a1;
            wmma::load_matrix_sync(a0, arow0 + kt * 8, 68);
            wmma::load_matrix_sync(a1, arow1 + kt * 8, 68);
#pragma unroll
            for (int i = 0; i < a0.num_elements; i++) {
                a0.x[i] = wmma::__float_to_tf32(a0.x[i]);
                a1.x[i] = wmma::__float_to_tf32(a1.x[i]);
            }
#pragma unroll
            for (int nt = 0; nt < 4; nt++) {
                wmma::fragment<wmma::matrix_b, 16, 16, 8, wmma::precision::tf32, wmma::row_major> b;
                wmma::load_matrix_sync(b, &sB[(ch * 64 + kt * 8) * 128 + dimbase + nt * 16], 128);
                wmma::mma_sync(acc[0][nt], a0, b, acc[0][nt]);
                wmma::mma_sync(acc[1][nt], a1, b, acc[1][nt]);
            }
        }
    }

    __syncthreads();

    float* stage = sm + warp * 2176;
#pragma unroll
    for (int mt = 0; mt < 2; mt++)
#pragma unroll
        for (int nt = 0; nt < 4; nt++)
            wmma::store_matrix_sync(stage + mt * 16 * 68 + nt * 16, acc[mt][nt], 68,
                                    wmma::mem_row_major);
    __syncwarp();

#pragma unroll 4
    for (int r = 0; r < 32; r++) {
        int node = nbase + ngrp * 32 + r;
        if (node < N_NODES) {
            float2 v = *(const float2*)&stage[r * 68 + lane * 2];
            *(float2*)&g_h[(long)node * HD + dimbase + lane * 2] = v;
        }
    }
    // att dots: lane = node, float4-vectorized 64-dim dot
    {
        const float* row = &stage[lane * 68];
        float ps = 0.f, pd = 0.f;
#pragma unroll
        for (int j = 0; j < 64; j += 4) {
            float4 h4 = *(const float4*)&row[j];
            float4 s4 = *(const float4*)&satt[dimbase + j];
            float4 d4 = *(const float4*)&satt[128 + dimbase + j];
            ps += h4.x * s4.x + h4.y * s4.y + h4.z * s4.z + h4.w * s4.w;
            pd += h4.x * d4.x + h4.y * d4.y + h4.z * d4.z + h4.w * d4.w;
        }
        int node = nbase + ngrp * 32 + lane;
        if (node < N_NODES) {
            g_ssrc[node * 2 + half] = ps;
            g_sdst[node * 2 + half] = pd;
        }
    }
}

// ---------------- CSR build (unordered segments) ----------------
__global__ void k_assign() {
    const int n    = blockIdx.x * 256 + threadIdx.x;
    const int lane = threadIdx.x & 31;
    int deg = (n < N_NODES) ? g_deg[n] : 0;
    int scan = deg;
#pragma unroll
    for (int o = 1; o < 32; o <<= 1) {
        int v = __shfl_up_sync(0xffffffffu, scan, o);
        if (lane >= o) scan += v;
    }
    int wtot = __shfl_sync(0xffffffffu, scan, 31);
    int base = 0;
    if (lane == 31) base = atomicAdd(&g_total, wtot);
    base = __shfl_sync(0xffffffffu, base, 31);
    int start = base + scan - deg;
    if (n < N_NODES) {
        g_se[n * 2 + 0] = start;
        g_se[n * 2 + 1] = start + deg;
        g_cur[n] = start;
    }
}

__global__ void k_scatter(const int* __restrict__ ei, const int* __restrict__ etyp) {
    int e = blockIdx.x * 256 + threadIdx.x;
    if (e >= N_EDGES) return;
    const int dst = ei[N_EDGES + e];
    int pos = atomicAdd(&g_cur[dst], 1);
    g_edge[pos] = make_int2(ei[e], etyp[e]);
}

// ---------------- fused per-dst softmax (max-free) + aggregation + tanh ----------------
__global__ void __launch_bounds__(256) k_agg(float* __restrict__ xout) {
    __shared__ float rp[NREL * HD];
    __shared__ int   sm_s[8][32];
    __shared__ int   sm_t[8][32];
    __shared__ float sm_a[8][2][32];
    const int tid = threadIdx.x;
    for (int i = tid; i < NREL * HD; i += 256) rp[i] = g_rproj[i];
    __syncthreads();

    const int lane = tid & 31;
    const int wid  = tid >> 5;
    const int head = lane >> 4;
    const int nwarps = gridDim.x * 8;

    for (int dst = blockIdx.x * 8 + wid; dst < N_NODES; dst += nwarps) {
        const int2 se  = ((const int2*)g_se)[dst];
        const int start = se.x, end = se.y;
        const int deg   = end - start;
        const float2 sd = ((const float2*)g_sdst)[dst];
        float4 acc = make_float4(0.f, 0.f, 0.f, 0.f);

        if (deg <= 32) {
            // single pass, no max subtraction (logits are small; softmax identical)
            const int i = start + lane;
            const bool v = (i < end);
            int s = 0, t = 0;
            float e0 = 0.f, e1 = 0.f;
            if (v) {
                int2 ed = g_edge[i];
                s = ed.x; t = ed.y;
                float2 ss = ((const float2*)g_ssrc)[s];
                float2 sr = ((const float2*)g_srel)[t];
                float l0 = ss.x + sr.x + sd.x; l0 = (l0 > 0.f) ? l0 : 0.2f * l0;
                float l1 = ss.y + sr.y + sd.y; l1 = (l1 > 0.f) ? l1 : 0.2f * l1;
                e0 = __expf(l0);
                e1 = __expf(l1);
            }
            float d0 = e0, d1 = e1;
#pragma unroll
            for (int o = 16; o > 0; o >>= 1) {
                d0 += __shfl_xor_sync(0xffffffffu, d0, o);
                d1 += __shfl_xor_sync(0xffffffffu, d1, o);
            }
            sm_s[wid][lane] = s;
            sm_t[wid][lane] = t;
            sm_a[wid][0][lane] = e0 / (d0 + 1e-16f);
            sm_a[wid][1][lane] = e1 / (d1 + 1e-16f);
            __syncwarp();
            for (int j = 0; j < deg; j++) {
                const int   sj = sm_s[wid][j];
                const int   tj = sm_t[wid][j];
                const float aj = sm_a[wid][head][j];
                float4 hv = *(const float4*)&g_h[(long)sj * HD + lane * 4];
                float4 rv = *(const float4*)&rp[tj * HD + lane * 4];
                acc.x += aj * (hv.x + rv.x);
                acc.y += aj * (hv.y + rv.y);
                acc.z += aj * (hv.z + rv.z);
                acc.w += aj * (hv.w + rv.w);
            }
        } else {
            // two-pass (denominator, then weighted gather), no max subtraction
            float d0 = 0.f, d1 = 0.f;
            for (int i = start + lane; i < end; i += 32) {
                int2 ed = g_edge[i];
                float2 ss = ((const float2*)g_ssrc)[ed.x];
                float2 sr = ((const float2*)g_srel)[ed.y];
                float l0 = ss.x + sr.x + sd.x; l0 = (l0 > 0.f) ? l0 : 0.2f * l0;
                float l1 = ss.y + sr.y + sd.y; l1 = (l1 > 0.f) ? l1 : 0.2f * l1;
                d0 += __expf(l0); d1 += __expf(l1);
            }
#pragma unroll
            for (int o = 16; o > 0; o >>= 1) {
                d0 += __shfl_xor_sync(0xffffffffu, d0, o);
                d1 += __shfl_xor_sync(0xffffffffu, d1, o);
            }
            const float inv0 = 1.f / (d0 + 1e-16f);
            const float inv1 = 1.f / (d1 + 1e-16f);
            for (int base = start; base < end; base += 32) {
                const int i = base + lane;
                int s = 0, t = 0;
                float a0 = 0.f, a1 = 0.f;
                if (i < end) {
                    int2 ed = g_edge[i];
                    s = ed.x; t = ed.y;
                    float2 ss = ((const float2*)g_ssrc)[s];
                    float2 sr = ((const float2*)g_srel)[t];
                    float l0 = ss.x + sr.x + sd.x; l0 = (l0 > 0.f) ? l0 : 0.2f * l0;
                    float l1 = ss.y + sr.y + sd.y; l1 = (l1 > 0.f) ? l1 : 0.2f * l1;
                    a0 = __expf(l0) * inv0;
                    a1 = __expf(l1) * inv1;
                }
                sm_s[wid][lane] = s;
                sm_t[wid][lane] = t;
                sm_a[wid][0][lane] = a0;
                sm_a[wid][1][lane] = a1;
                __syncwarp();
                const int cnt = min(32, end - base);
                for (int j = 0; j < cnt; j++) {
                    const int   sj = sm_s[wid][j];
                    const int   tj = sm_t[wid][j];
                    const float aj = sm_a[wid][head][j];
                    float4 hv = *(const float4*)&g_h[(long)sj * HD + lane * 4];
                    float4 rv = *(const float4*)&rp[tj * HD + lane * 4];
                    acc.x += aj * (hv.x + rv.x);
                    acc.y += aj * (hv.y + rv.y);
                    acc.z += aj * (hv.z + rv.z);
                    acc.w += aj * (hv.w + rv.w);
                }
                __syncwarp();
            }
        }
        acc.x = tanh_approx(acc.x);
        acc.y = tanh_approx(acc.y);
        acc.z = tanh_approx(acc.z);
        acc.w = tanh_approx(acc.w);
        *(float4*)&xout[(long)dst * HD + lane * 4] = acc;
    }
}

__global__ void k_gather(const int* __restrict__ sub, const float* __restrict__ xout,
                         float* __restrict__ sub_emb) {
    int b = blockIdx.x;
    int d = threadIdx.x;
    sub_emb[(long)b * HD + d] = xout[(long)sub[b] * HD + d];
}

// ---------------- launch ----------------
extern "C" void kernel_launch(void* const* d_in, const int* in_sizes, int n_in,
                              void* d_out, int out_size) {
    const int*   edge_index  = (const int*)d_in[0];
    const int*   edge_type   = (const int*)d_in[1];
    const int*   ent_feature = (const int*)d_in[3];
    const int*   sub         = (const int*)d_in[4];
    const float* id_embed    = (const float*)d_in[7];
    const float* gender_tab  = (const float*)d_in[8];
    const float* age_tab     = (const float*)d_in[9];
    const float* level_tab   = (const float*)d_in[10];
    const float* init_rel    = (const float*)d_in[11];
    const float* W           = (const float*)d_in[12];
    const float* Wr          = (const float*)d_in[13];
    const float* att_src     = (const float*)d_in[14];
    const float* att_dst     = (const float*)d_in[15];
    const float* Wrel        = (const float*)d_in[16];

    float* out     = (float*)d_out;
    float* sub_emb = out;
    float* rout    = out + (long)BATCH * HD;
    float* xout    = rout + (long)NREL * HD;

    const int smem_kh = (8704 + 16384 + 256) * 4;
    cudaFuncSetAttribute(k_h, cudaFuncAttributeMaxDynamicSharedMemorySize, smem_kh);

    k_prep<<<223 + 49, 512>>>(gender_tab, age_tab, level_tab, init_rel, W, Wr, Wrel,
                              att_src, rout);
    k_wextdeg<<<64 + (N_EDGES + 255) / 256, 256>>>(W, edge_index);
    k_assign<<<(N_NODES + 255) / 256, 256>>>();
    k_h<<<(N_NODES + 127) / 128, 256, smem_kh>>>(id_embed, ent_feature,
                                                 att_src, att_dst);  // profile idx 3
    k_scatter<<<(N_EDGES + 255) / 256, 256>>>(edge_index, edge_type);
    k_agg<<<592, 256>>>(xout);
    k_gather<<<BATCH, 128>>>(sub, xout, sub_emb);
}